// round 1
// baseline (speedup 1.0000x reference)
#include <cuda_runtime.h>
#include <math.h>

// Problem constants
#define BATCH 4
#define SEQ   2048
#define DIM   2048
#define HEADS 16
#define HDIM  128
#define MTOK  (BATCH * SEQ)          // 8192 tokens
#define NROWS_NORM (MTOK * HEADS)    // 131072 (token,head) rows of 128

// -------------------- scratch (device globals; no cudaMalloc allowed) ------
__device__ float g_q[(size_t)MTOK * DIM];
__device__ float g_k[(size_t)MTOK * DIM];
__device__ float g_v[(size_t)MTOK * DIM];
__device__ float g_o[(size_t)MTOK * DIM];

// ---------------------------------------------------------------------------
// GEMM: C[M,N] = A[M,K] @ W[N,K]^T + bias[N]     (torch Linear semantics)
// 128x128 block tile, BK=16, 256 threads, 8x8 per-thread microtile.
// ---------------------------------------------------------------------------
__global__ void __launch_bounds__(256, 2)
gemm_bias_kernel(const float* __restrict__ A, const float* __restrict__ W,
                 const float* __restrict__ bias, float* __restrict__ C,
                 int M, int N, int K)
{
    __shared__ float sA[128][20];   // [row][k], pitch 20 keeps float4 stores aligned
    __shared__ float sW[128][20];

    const int tid = threadIdx.x;
    const int tx = tid & 15;        // N direction
    const int ty = tid >> 4;        // M direction
    const int m0 = blockIdx.y * 128;
    const int n0 = blockIdx.x * 128;

    float acc[8][8];
#pragma unroll
    for (int i = 0; i < 8; i++)
#pragma unroll
        for (int j = 0; j < 8; j++) acc[i][j] = 0.f;

    for (int k0 = 0; k0 < K; k0 += 16) {
        // load 128x16 tiles of A and W (row-major, K contiguous)
#pragma unroll
        for (int l = 0; l < 2; l++) {
            int idx  = tid + l * 256;        // 0..511
            int row  = idx >> 2;             // 0..127
            int quad = (idx & 3) << 2;       // 0,4,8,12
            float4 av = *(const float4*)&A[(size_t)(m0 + row) * K + k0 + quad];
            *(float4*)&sA[row][quad] = av;
            float4 wv = *(const float4*)&W[(size_t)(n0 + row) * K + k0 + quad];
            *(float4*)&sW[row][quad] = wv;
        }
        __syncthreads();

#pragma unroll
        for (int kk = 0; kk < 16; kk++) {
            float a[8], b[8];
#pragma unroll
            for (int i = 0; i < 8; i++) a[i] = sA[ty + 16 * i][kk];
#pragma unroll
            for (int j = 0; j < 8; j++) b[j] = sW[tx + 16 * j][kk];
#pragma unroll
            for (int i = 0; i < 8; i++)
#pragma unroll
                for (int j = 0; j < 8; j++)
                    acc[i][j] = fmaf(a[i], b[j], acc[i][j]);
        }
        __syncthreads();
    }

#pragma unroll
    for (int j = 0; j < 8; j++) {
        int col = n0 + tx + 16 * j;
        float bj = bias[col];
#pragma unroll
        for (int i = 0; i < 8; i++) {
            C[(size_t)(m0 + ty + 16 * i) * N + col] = acc[i][j] + bj;
        }
    }
}

// ---------------------------------------------------------------------------
// RMSNorm over head_dim=128: one warp per (token,head) row of 128 contiguous
// floats; x <- x * rsqrt(mean(x^2)+eps) * w
// ---------------------------------------------------------------------------
__global__ void __launch_bounds__(256)
rmsnorm_kernel(float* __restrict__ x, const float* __restrict__ w, int nrows)
{
    int gwarp = (blockIdx.x * blockDim.x + threadIdx.x) >> 5;
    int lane  = threadIdx.x & 31;
    if (gwarp >= nrows) return;

    float4 v = *(float4*)&x[(size_t)gwarp * 128 + lane * 4];
    float ss = v.x * v.x + v.y * v.y + v.z * v.z + v.w * v.w;
#pragma unroll
    for (int off = 16; off >= 1; off >>= 1)
        ss += __shfl_xor_sync(0xffffffffu, ss, off);
    float r = rsqrtf(ss * (1.0f / 128.0f) + 1e-6f);
    float4 wv = *(const float4*)&w[lane * 4];
    v.x *= r * wv.x; v.y *= r * wv.y; v.z *= r * wv.z; v.w *= r * wv.w;
    *(float4*)&x[(size_t)gwarp * 128 + lane * 4] = v;
}

// ---------------------------------------------------------------------------
// Flash-style attention, fp32. One CTA = one (b,h) and 64 q rows.
// Streams K/V in 64-row tiles with online softmax. 256 threads:
// thread (ty,tx) owns rows r_i = ty+16i (i<4), score cols c_j = tx+16j (j<4),
// O cols tx+16j (j<8).
// ---------------------------------------------------------------------------
#define SQ_PITCH 132
#define ATTN_SMEM_FLOATS (64 * SQ_PITCH * 2 + 64 * 128 + 64 * 64)
#define ATTN_SMEM_BYTES  (ATTN_SMEM_FLOATS * 4)

__global__ void __launch_bounds__(256, 1)
attn_kernel(const float* __restrict__ Qg, const float* __restrict__ Kg,
            const float* __restrict__ Vg, float* __restrict__ Og)
{
    extern __shared__ float smem[];
    float* sQ = smem;                       // [64][132]
    float* sK = sQ + 64 * SQ_PITCH;         // [64][132]
    float* sV = sK + 64 * SQ_PITCH;         // [64][128]
    float* sP = sV + 64 * 128;              // [64][64]

    const int tid = threadIdx.x;
    const int tx = tid & 15;
    const int ty = tid >> 4;
    const int sq0 = blockIdx.x * 64;
    const int bh  = blockIdx.y;
    const int b   = bh >> 4;
    const int h   = bh & 15;
    const float scale = 0.08838834764831845f;   // 1/sqrt(128)

    const float* Qb = Qg + (size_t)(b * SEQ + sq0) * DIM + h * HDIM;
    const float* Kb = Kg + (size_t)b * SEQ * DIM + h * HDIM;
    const float* Vb = Vg + (size_t)b * SEQ * DIM + h * HDIM;

    // load Q tile (pre-scaled)
#pragma unroll
    for (int t = 0; t < 8; t++) {
        int idx = tid + t * 256;            // 0..2047
        int row = idx >> 5;                 // 0..63
        int q4  = (idx & 31) << 2;          // 0..124
        float4 v = *(const float4*)&Qb[(size_t)row * DIM + q4];
        v.x *= scale; v.y *= scale; v.z *= scale; v.w *= scale;
        *(float4*)&sQ[row * SQ_PITCH + q4] = v;
    }

    float m[4], l[4], o[4][8];
#pragma unroll
    for (int i = 0; i < 4; i++) {
        m[i] = -1e30f; l[i] = 0.f;
#pragma unroll
        for (int j = 0; j < 8; j++) o[i][j] = 0.f;
    }

    for (int kt = 0; kt < SEQ / 64; kt++) {
        const float* Kt = Kb + (size_t)(kt * 64) * DIM;
        const float* Vt = Vb + (size_t)(kt * 64) * DIM;

        __syncthreads();   // previous PV done reading sV/sP; sQ visible on iter 0
#pragma unroll
        for (int t = 0; t < 8; t++) {
            int idx = tid + t * 256;
            int row = idx >> 5;
            int q4  = (idx & 31) << 2;
            *(float4*)&sK[row * SQ_PITCH + q4] = *(const float4*)&Kt[(size_t)row * DIM + q4];
            *(float4*)&sV[row * 128 + q4]      = *(const float4*)&Vt[(size_t)row * DIM + q4];
        }
        __syncthreads();

        // S tile (64x64): s[i][j] = q_row(ty+16i) . k_row(tx+16j)
        float s[4][4];
#pragma unroll
        for (int i = 0; i < 4; i++)
#pragma unroll
            for (int j = 0; j < 4; j++) s[i][j] = 0.f;

        for (int kk = 0; kk < 128; kk += 4) {
            float4 qv[4], kv[4];
#pragma unroll
            for (int i = 0; i < 4; i++)
                qv[i] = *(float4*)&sQ[(ty + 16 * i) * SQ_PITCH + kk];
#pragma unroll
            for (int j = 0; j < 4; j++)
                kv[j] = *(float4*)&sK[(tx + 16 * j) * SQ_PITCH + kk];
#pragma unroll
            for (int i = 0; i < 4; i++)
#pragma unroll
                for (int j = 0; j < 4; j++) {
                    s[i][j] = fmaf(qv[i].x, kv[j].x, s[i][j]);
                    s[i][j] = fmaf(qv[i].y, kv[j].y, s[i][j]);
                    s[i][j] = fmaf(qv[i].z, kv[j].z, s[i][j]);
                    s[i][j] = fmaf(qv[i].w, kv[j].w, s[i][j]);
                }
        }

        // online softmax (rows live across tx: reduce over the 16-lane group)
#pragma unroll
        for (int i = 0; i < 4; i++) {
            float rmax = s[i][0];
#pragma unroll
            for (int j = 1; j < 4; j++) rmax = fmaxf(rmax, s[i][j]);
#pragma unroll
            for (int off = 8; off >= 1; off >>= 1)
                rmax = fmaxf(rmax, __shfl_xor_sync(0xffffffffu, rmax, off));

            float mn = fmaxf(m[i], rmax);
            float alpha = __expf(m[i] - mn);

            float p[4], rsum = 0.f;
#pragma unroll
            for (int j = 0; j < 4; j++) { p[j] = __expf(s[i][j] - mn); rsum += p[j]; }
#pragma unroll
            for (int off = 8; off >= 1; off >>= 1)
                rsum += __shfl_xor_sync(0xffffffffu, rsum, off);

            l[i] = l[i] * alpha + rsum;
            m[i] = mn;
#pragma unroll
            for (int j = 0; j < 8; j++) o[i][j] *= alpha;
#pragma unroll
            for (int j = 0; j < 4; j++)
                sP[(ty + 16 * i) * 64 + tx + 16 * j] = p[j];
        }
        __syncthreads();

        // O += P @ V   (P: 64x64 in smem, V: 64x128 in smem)
#pragma unroll 4
        for (int k = 0; k < 64; k++) {
            float pv[4];
#pragma unroll
            for (int i = 0; i < 4; i++) pv[i] = sP[(ty + 16 * i) * 64 + k];
            float vv[8];
#pragma unroll
            for (int j = 0; j < 8; j++) vv[j] = sV[k * 128 + tx + 16 * j];
#pragma unroll
            for (int i = 0; i < 4; i++)
#pragma unroll
                for (int j = 0; j < 8; j++)
                    o[i][j] = fmaf(pv[i], vv[j], o[i][j]);
        }
    }

    // normalize and write O (back into [B,S,D] layout, head slice)
    float* Ob = Og + (size_t)(b * SEQ + sq0) * DIM + h * HDIM;
#pragma unroll
    for (int i = 0; i < 4; i++) {
        float inv = 1.0f / l[i];
#pragma unroll
        for (int j = 0; j < 8; j++)
            Ob[(size_t)(ty + 16 * i) * DIM + tx + 16 * j] = o[i][j] * inv;
    }
}

// ---------------------------------------------------------------------------
extern "C" void kernel_launch(void* const* d_in, const int* in_sizes, int n_in,
                              void* d_out, int out_size)
{
    const float* query = (const float*)d_in[0];
    const float* key   = (const float*)d_in[1];
    const float* value = (const float*)d_in[2];
    const float* Wq    = (const float*)d_in[3];
    const float* bq    = (const float*)d_in[4];
    const float* Wk    = (const float*)d_in[5];
    const float* bk    = (const float*)d_in[6];
    const float* Wv    = (const float*)d_in[7];
    const float* bv    = (const float*)d_in[8];
    const float* Wo    = (const float*)d_in[9];
    const float* bo    = (const float*)d_in[10];
    const float* qnw   = (const float*)d_in[11];
    const float* knw   = (const float*)d_in[12];
    float* out = (float*)d_out;

    float *gq, *gk, *gv, *go;
    cudaGetSymbolAddress((void**)&gq, g_q);
    cudaGetSymbolAddress((void**)&gk, g_k);
    cudaGetSymbolAddress((void**)&gv, g_v);
    cudaGetSymbolAddress((void**)&go, g_o);

    cudaFuncSetAttribute(attn_kernel,
                         cudaFuncAttributeMaxDynamicSharedMemorySize,
                         ATTN_SMEM_BYTES);

    dim3 gemm_grid(DIM / 128, MTOK / 128);   // (16, 64)

    // Q/K/V projections
    gemm_bias_kernel<<<gemm_grid, 256>>>(query, Wq, bq, gq, MTOK, DIM, DIM);
    gemm_bias_kernel<<<gemm_grid, 256>>>(key,   Wk, bk, gk, MTOK, DIM, DIM);
    gemm_bias_kernel<<<gemm_grid, 256>>>(value, Wv, bv, gv, MTOK, DIM, DIM);

    // per-head RMSNorm on q and k
    int norm_blocks = NROWS_NORM / 8;        // 8 warps per 256-thread block
    rmsnorm_kernel<<<norm_blocks, 256>>>(gq, qnw, NROWS_NORM);
    rmsnorm_kernel<<<norm_blocks, 256>>>(gk, knw, NROWS_NORM);

    // attention
    dim3 attn_grid(SEQ / 64, BATCH * HEADS); // (32, 64)
    attn_kernel<<<attn_grid, 256, ATTN_SMEM_BYTES>>>(gq, gk, gv, go);

    // output projection
    gemm_bias_kernel<<<gemm_grid, 256>>>(go, Wo, bo, out, MTOK, DIM, DIM);
}

// round 3
// speedup vs baseline: 1.3721x; 1.3721x over previous
#include <cuda_runtime.h>
#include <cuda_bf16.h>
#include <math.h>
#include <stdint.h>

// Problem constants
#define BATCH 4
#define SEQ   2048
#define DIM   2048
#define HEADS 16
#define HDIM  128
#define MTOK  (BATCH * SEQ)          // 8192 tokens
#define NROWS_NORM (MTOK * HEADS)    // 131072 (token,head) rows of 128
#define KP    (3 * DIM)              // 6144 split-bf16 K'

// -------------------- scratch (device globals; no cudaMalloc allowed) ------
__device__ float g_q[(size_t)MTOK * DIM];
__device__ float g_k[(size_t)MTOK * DIM];
__device__ float g_v[(size_t)MTOK * DIM];
__device__ float g_o[(size_t)MTOK * DIM];
__device__ __align__(1024) __nv_bfloat16 g_a2[(size_t)MTOK * KP];  // split activations
__device__ __align__(1024) __nv_bfloat16 g_w2[(size_t)DIM * KP];   // split weights

// ===========================================================================
// helpers
// ===========================================================================
__device__ __forceinline__ uint32_t smem_u32(const void* p) {
    uint32_t a;
    asm("{ .reg .u64 t; cvta.to.shared.u64 t, %1; cvt.u32.u64 %0, t; }"
        : "=r"(a) : "l"(p));
    return a;
}

__device__ __forceinline__ void cp_async16(uint32_t saddr, const void* gptr) {
    asm volatile("cp.async.cg.shared.global [%0], [%1], 16;"
                 :: "r"(saddr), "l"(gptr) : "memory");
}

__device__ __forceinline__ void ldmatrix_x4(uint32_t& r0, uint32_t& r1,
                                            uint32_t& r2, uint32_t& r3,
                                            uint32_t addr) {
    asm volatile("ldmatrix.sync.aligned.m8n8.x4.shared.b16 {%0,%1,%2,%3}, [%4];"
                 : "=r"(r0), "=r"(r1), "=r"(r2), "=r"(r3) : "r"(addr));
}

__device__ __forceinline__ void mma_bf16(float* c, const uint32_t* a,
                                         uint32_t b0, uint32_t b1) {
    asm volatile(
        "mma.sync.aligned.m16n8k16.row.col.f32.bf16.bf16.f32 "
        "{%0,%1,%2,%3}, {%4,%5,%6,%7}, {%8,%9}, {%0,%1,%2,%3};"
        : "+f"(c[0]), "+f"(c[1]), "+f"(c[2]), "+f"(c[3])
        : "r"(a[0]), "r"(a[1]), "r"(a[2]), "r"(a[3]), "r"(b0), "r"(b1));
}

// ===========================================================================
// split conversion kernels: x = hi + lo (bf16 pair)
// A': [hi | hi | lo], W': [hi | lo | hi]   (rows of K'=6144)
// ===========================================================================
__global__ void __launch_bounds__(256)
split_a_kernel(const float* __restrict__ x, __nv_bfloat16* __restrict__ out)
{
    int idx = blockIdx.x * 256 + threadIdx.x;           // one float2 per thread
    int m = idx / (DIM / 2);
    int k2 = idx % (DIM / 2);
    float2 v = *(const float2*)&x[(size_t)m * DIM + k2 * 2];
    __nv_bfloat16 h0 = __float2bfloat16(v.x);
    __nv_bfloat16 h1 = __float2bfloat16(v.y);
    __nv_bfloat16 l0 = __float2bfloat16(v.x - __bfloat162float(h0));
    __nv_bfloat16 l1 = __float2bfloat16(v.y - __bfloat162float(h1));
    __nv_bfloat162 hi2; hi2.x = h0; hi2.y = h1;
    __nv_bfloat162 lo2; lo2.x = l0; lo2.y = l1;
    __nv_bfloat162* row = (__nv_bfloat162*)&out[(size_t)m * KP];
    row[k2] = hi2;
    row[DIM / 2 + k2] = hi2;
    row[DIM + k2] = lo2;
}

__global__ void __launch_bounds__(256)
split_w_kernel(const float* __restrict__ x, __nv_bfloat16* __restrict__ out)
{
    int idx = blockIdx.x * 256 + threadIdx.x;
    int m = idx / (DIM / 2);
    int k2 = idx % (DIM / 2);
    float2 v = *(const float2*)&x[(size_t)m * DIM + k2 * 2];
    __nv_bfloat16 h0 = __float2bfloat16(v.x);
    __nv_bfloat16 h1 = __float2bfloat16(v.y);
    __nv_bfloat16 l0 = __float2bfloat16(v.x - __bfloat162float(h0));
    __nv_bfloat16 l1 = __float2bfloat16(v.y - __bfloat162float(h1));
    __nv_bfloat162 hi2; hi2.x = h0; hi2.y = h1;
    __nv_bfloat162 lo2; lo2.x = l0; lo2.y = l1;
    __nv_bfloat162* row = (__nv_bfloat162*)&out[(size_t)m * KP];
    row[k2] = hi2;
    row[DIM / 2 + k2] = lo2;
    row[DIM + k2] = hi2;
}

// ===========================================================================
// HMMA GEMM via mma.sync: C[M,N] = A'[M,K'] @ W'[N,K']^T + bias
// CTA 128x128, BK=64, 3-stage cp.async pipeline, 8 warps (2x4), warp 64x32.
// smem pitch 72 bf16 (144B) -> conflict-free STS.128 and ldmatrix.
// ===========================================================================
#define BK       64
#define PITCH    72
#define PITCHB   (PITCH * 2)                  // 144 bytes
#define TILEAB   (128 * PITCHB)               // 18432 B per operand tile
#define STAGE_B  (2 * TILEAB)                 // 36864 B per stage
#define STAGES   3
#define NCHUNK   (KP / BK)                    // 96
#define GEMM_SMEM (STAGES * STAGE_B)          // 110592 B

__global__ void __launch_bounds__(256, 1)
gemm_mma_kernel(const __nv_bfloat16* __restrict__ Ap,
                const __nv_bfloat16* __restrict__ Bp,
                const float* __restrict__ bias, float* __restrict__ C, int N)
{
    extern __shared__ __align__(1024) char smem[];
    const uint32_t sbase = smem_u32(smem);
    const int tid  = threadIdx.x;
    const int lane = tid & 31;
    const int wid  = tid >> 5;
    const int wm   = (wid >> 2) * 64;          // warp M offset in tile
    const int wn   = (wid & 3) * 32;           // warp N offset in tile
    const int m0   = blockIdx.y * 128;
    const int n0   = blockIdx.x * 128;

    const __nv_bfloat16* Abase = Ap + (size_t)m0 * KP;
    const __nv_bfloat16* Bbase = Bp + (size_t)n0 * KP;

    // loader: each thread moves 4 x 16B for A and 4 x 16B for B
    const int lrow = tid >> 1;                 // 0..127
    const int lcol = (tid & 1) * 4;            // chunk base 0 or 4 (of 8)
    auto load_tile = [&](int s, int c) {
        const uint32_t sa = sbase + s * STAGE_B;
        const uint32_t sb = sa + TILEAB;
        const __nv_bfloat16* Ag = Abase + (size_t)lrow * KP + c * BK + lcol * 8;
        const __nv_bfloat16* Bg = Bbase + (size_t)lrow * KP + c * BK + lcol * 8;
        const uint32_t so = lrow * PITCHB + lcol * 16;
        #pragma unroll
        for (int i = 0; i < 4; i++) {
            cp_async16(sa + so + i * 16, Ag + i * 8);
            cp_async16(sb + so + i * 16, Bg + i * 8);
        }
        asm volatile("cp.async.commit_group;" ::: "memory");
    };

    float acc[4][4][4];
    #pragma unroll
    for (int mi = 0; mi < 4; mi++)
        #pragma unroll
        for (int ni = 0; ni < 4; ni++)
            #pragma unroll
            for (int r = 0; r < 4; r++) acc[mi][ni][r] = 0.f;

    // prologue
    load_tile(0, 0);
    load_tile(1, 1);

    // per-lane ldmatrix address components
    const uint32_t arow = wm + (lane & 15);
    const uint32_t brow = wn + (lane & 15);
    const uint32_t koff = (lane >> 4) * 16;    // 0 or 16 bytes (8 bf16)

    for (int c = 0; c < NCHUNK; c++) {
        const int s = c % STAGES;
        asm volatile("cp.async.wait_group 1;" ::: "memory");
        __syncthreads();

        const uint32_t sa = sbase + s * STAGE_B + arow * PITCHB + koff;
        const uint32_t sb = sbase + s * STAGE_B + TILEAB + brow * PITCHB + koff;

        #pragma unroll
        for (int ks = 0; ks < 4; ks++) {
            uint32_t a[4][4];
            #pragma unroll
            for (int mi = 0; mi < 4; mi++)
                ldmatrix_x4(a[mi][0], a[mi][1], a[mi][2], a[mi][3],
                            sa + mi * 16 * PITCHB + ks * 32);
            uint32_t b[2][4];
            #pragma unroll
            for (int nb = 0; nb < 2; nb++)
                ldmatrix_x4(b[nb][0], b[nb][1], b[nb][2], b[nb][3],
                            sb + nb * 16 * PITCHB + ks * 32);
            #pragma unroll
            for (int mi = 0; mi < 4; mi++)
                #pragma unroll
                for (int ni = 0; ni < 4; ni++)
                    mma_bf16(acc[mi][ni], a[mi],
                             b[ni >> 1][ni & 1], b[ni >> 1][(ni & 1) + 2]);
        }

        __syncthreads();
        const int y = c + 2;
        if (y < NCHUNK) load_tile(y % STAGES, y);
        else asm volatile("cp.async.commit_group;" ::: "memory"); // keep group count uniform
    }

    // epilogue: c0,c1 -> (row, col..col+1); c2,c3 -> (row+8, ...)
    #pragma unroll
    for (int mi = 0; mi < 4; mi++) {
        const int r = m0 + wm + mi * 16 + (lane >> 2);
        #pragma unroll
        for (int ni = 0; ni < 4; ni++) {
            const int col = n0 + wn + ni * 8 + (lane & 3) * 2;
            float2 v0, v1;
            v0.x = acc[mi][ni][0] + bias[col];
            v0.y = acc[mi][ni][1] + bias[col + 1];
            v1.x = acc[mi][ni][2] + bias[col];
            v1.y = acc[mi][ni][3] + bias[col + 1];
            *(float2*)&C[(size_t)r * N + col]       = v0;
            *(float2*)&C[(size_t)(r + 8) * N + col] = v1;
        }
    }
}

// ---------------------------------------------------------------------------
// RMSNorm over head_dim=128
// ---------------------------------------------------------------------------
__global__ void __launch_bounds__(256)
rmsnorm_kernel(float* __restrict__ x, const float* __restrict__ w, int nrows)
{
    int gwarp = (blockIdx.x * blockDim.x + threadIdx.x) >> 5;
    int lane  = threadIdx.x & 31;
    if (gwarp >= nrows) return;

    float4 v = *(float4*)&x[(size_t)gwarp * 128 + lane * 4];
    float ss = v.x * v.x + v.y * v.y + v.z * v.z + v.w * v.w;
#pragma unroll
    for (int off = 16; off >= 1; off >>= 1)
        ss += __shfl_xor_sync(0xffffffffu, ss, off);
    float r = rsqrtf(ss * (1.0f / 128.0f) + 1e-6f);
    float4 wv = *(const float4*)&w[lane * 4];
    v.x *= r * wv.x; v.y *= r * wv.y; v.z *= r * wv.z; v.w *= r * wv.w;
    *(float4*)&x[(size_t)gwarp * 128 + lane * 4] = v;
}

// ---------------------------------------------------------------------------
// Flash-style attention, fp32 SIMT (unchanged this round)
// ---------------------------------------------------------------------------
#define SQ_PITCH 132
#define ATTN_SMEM_FLOATS (64 * SQ_PITCH * 2 + 64 * 128 + 64 * 64)
#define ATTN_SMEM_BYTES  (ATTN_SMEM_FLOATS * 4)

__global__ void __launch_bounds__(256, 1)
attn_kernel(const float* __restrict__ Qg, const float* __restrict__ Kg,
            const float* __restrict__ Vg, float* __restrict__ Og)
{
    extern __shared__ float fsmem[];
    float* sQ = fsmem;
    float* sK = sQ + 64 * SQ_PITCH;
    float* sV = sK + 64 * SQ_PITCH;
    float* sP = sV + 64 * 128;

    const int tid = threadIdx.x;
    const int tx = tid & 15;
    const int ty = tid >> 4;
    const int sq0 = blockIdx.x * 64;
    const int bh  = blockIdx.y;
    const int b   = bh >> 4;
    const int h   = bh & 15;
    const float scale = 0.08838834764831845f;

    const float* Qb = Qg + (size_t)(b * SEQ + sq0) * DIM + h * HDIM;
    const float* Kb = Kg + (size_t)b * SEQ * DIM + h * HDIM;
    const float* Vb = Vg + (size_t)b * SEQ * DIM + h * HDIM;

#pragma unroll
    for (int t = 0; t < 8; t++) {
        int idx = tid + t * 256;
        int row = idx >> 5;
        int q4  = (idx & 31) << 2;
        float4 v = *(const float4*)&Qb[(size_t)row * DIM + q4];
        v.x *= scale; v.y *= scale; v.z *= scale; v.w *= scale;
        *(float4*)&sQ[row * SQ_PITCH + q4] = v;
    }

    float m[4], l[4], o[4][8];
#pragma unroll
    for (int i = 0; i < 4; i++) {
        m[i] = -1e30f; l[i] = 0.f;
#pragma unroll
        for (int j = 0; j < 8; j++) o[i][j] = 0.f;
    }

    for (int kt = 0; kt < SEQ / 64; kt++) {
        const float* Kt = Kb + (size_t)(kt * 64) * DIM;
        const float* Vt = Vb + (size_t)(kt * 64) * DIM;

        __syncthreads();
#pragma unroll
        for (int t = 0; t < 8; t++) {
            int idx = tid + t * 256;
            int row = idx >> 5;
            int q4  = (idx & 31) << 2;
            *(float4*)&sK[row * SQ_PITCH + q4] = *(const float4*)&Kt[(size_t)row * DIM + q4];
            *(float4*)&sV[row * 128 + q4]      = *(const float4*)&Vt[(size_t)row * DIM + q4];
        }
        __syncthreads();

        float s[4][4];
#pragma unroll
        for (int i = 0; i < 4; i++)
#pragma unroll
            for (int j = 0; j < 4; j++) s[i][j] = 0.f;

        for (int kk = 0; kk < 128; kk += 4) {
            float4 qv[4], kv[4];
#pragma unroll
            for (int i = 0; i < 4; i++)
                qv[i] = *(float4*)&sQ[(ty + 16 * i) * SQ_PITCH + kk];
#pragma unroll
            for (int j = 0; j < 4; j++)
                kv[j] = *(float4*)&sK[(tx + 16 * j) * SQ_PITCH + kk];
#pragma unroll
            for (int i = 0; i < 4; i++)
#pragma unroll
                for (int j = 0; j < 4; j++) {
                    s[i][j] = fmaf(qv[i].x, kv[j].x, s[i][j]);
                    s[i][j] = fmaf(qv[i].y, kv[j].y, s[i][j]);
                    s[i][j] = fmaf(qv[i].z, kv[j].z, s[i][j]);
                    s[i][j] = fmaf(qv[i].w, kv[j].w, s[i][j]);
                }
        }

#pragma unroll
        for (int i = 0; i < 4; i++) {
            float rmax = s[i][0];
#pragma unroll
            for (int j = 1; j < 4; j++) rmax = fmaxf(rmax, s[i][j]);
#pragma unroll
            for (int off = 8; off >= 1; off >>= 1)
                rmax = fmaxf(rmax, __shfl_xor_sync(0xffffffffu, rmax, off));

            float mn = fmaxf(m[i], rmax);
            float alpha = __expf(m[i] - mn);

            float p[4], rsum = 0.f;
#pragma unroll
            for (int j = 0; j < 4; j++) { p[j] = __expf(s[i][j] - mn); rsum += p[j]; }
#pragma unroll
            for (int off = 8; off >= 1; off >>= 1)
                rsum += __shfl_xor_sync(0xffffffffu, rsum, off);

            l[i] = l[i] * alpha + rsum;
            m[i] = mn;
#pragma unroll
            for (int j = 0; j < 8; j++) o[i][j] *= alpha;
#pragma unroll
            for (int j = 0; j < 4; j++)
                sP[(ty + 16 * i) * 64 + tx + 16 * j] = p[j];
        }
        __syncthreads();

#pragma unroll 4
        for (int k = 0; k < 64; k++) {
            float pv[4];
#pragma unroll
            for (int i = 0; i < 4; i++) pv[i] = sP[(ty + 16 * i) * 64 + k];
            float vv[8];
#pragma unroll
            for (int j = 0; j < 8; j++) vv[j] = sV[k * 128 + tx + 16 * j];
#pragma unroll
            for (int i = 0; i < 4; i++)
#pragma unroll
                for (int j = 0; j < 8; j++)
                    o[i][j] = fmaf(pv[i], vv[j], o[i][j]);
        }
    }

    float* Ob = Og + (size_t)(b * SEQ + sq0) * DIM + h * HDIM;
#pragma unroll
    for (int i = 0; i < 4; i++) {
        float inv = 1.0f / l[i];
#pragma unroll
        for (int j = 0; j < 8; j++)
            Ob[(size_t)(ty + 16 * i) * DIM + tx + 16 * j] = o[i][j] * inv;
    }
}

// ---------------------------------------------------------------------------
extern "C" void kernel_launch(void* const* d_in, const int* in_sizes, int n_in,
                              void* d_out, int out_size)
{
    const float* query = (const float*)d_in[0];
    const float* key   = (const float*)d_in[1];
    const float* value = (const float*)d_in[2];
    const float* Wq    = (const float*)d_in[3];
    const float* bq    = (const float*)d_in[4];
    const float* Wk    = (const float*)d_in[5];
    const float* bk    = (const float*)d_in[6];
    const float* Wv    = (const float*)d_in[7];
    const float* bv    = (const float*)d_in[8];
    const float* Wo    = (const float*)d_in[9];
    const float* bo    = (const float*)d_in[10];
    const float* qnw   = (const float*)d_in[11];
    const float* knw   = (const float*)d_in[12];
    float* out = (float*)d_out;

    float *gq, *gk, *gv, *go;
    __nv_bfloat16 *ga2, *gw2;
    cudaGetSymbolAddress((void**)&gq, g_q);
    cudaGetSymbolAddress((void**)&gk, g_k);
    cudaGetSymbolAddress((void**)&gv, g_v);
    cudaGetSymbolAddress((void**)&go, g_o);
    cudaGetSymbolAddress((void**)&ga2, g_a2);
    cudaGetSymbolAddress((void**)&gw2, g_w2);

    cudaFuncSetAttribute(attn_kernel,
                         cudaFuncAttributeMaxDynamicSharedMemorySize,
                         ATTN_SMEM_BYTES);
    cudaFuncSetAttribute(gemm_mma_kernel,
                         cudaFuncAttributeMaxDynamicSharedMemorySize,
                         GEMM_SMEM);

    const int convA_blocks = MTOK * (DIM / 2) / 256;   // 32768
    const int convW_blocks = DIM * (DIM / 2) / 256;    // 8192
    dim3 gemm_grid(DIM / 128, MTOK / 128);             // (16, 64)

    // Q projection
    split_w_kernel<<<convW_blocks, 256>>>(Wq, gw2);
    split_a_kernel<<<convA_blocks, 256>>>(query, ga2);
    gemm_mma_kernel<<<gemm_grid, 256, GEMM_SMEM>>>(ga2, gw2, bq, gq, DIM);
    // K projection
    split_w_kernel<<<convW_blocks, 256>>>(Wk, gw2);
    split_a_kernel<<<convA_blocks, 256>>>(key, ga2);
    gemm_mma_kernel<<<gemm_grid, 256, GEMM_SMEM>>>(ga2, gw2, bk, gk, DIM);
    // V projection
    split_w_kernel<<<convW_blocks, 256>>>(Wv, gw2);
    split_a_kernel<<<convA_blocks, 256>>>(value, ga2);
    gemm_mma_kernel<<<gemm_grid, 256, GEMM_SMEM>>>(ga2, gw2, bv, gv, DIM);

    // per-head RMSNorm on q and k
    int norm_blocks = NROWS_NORM / 8;
    rmsnorm_kernel<<<norm_blocks, 256>>>(gq, qnw, NROWS_NORM);
    rmsnorm_kernel<<<norm_blocks, 256>>>(gk, knw, NROWS_NORM);

    // attention (fp32 SIMT)
    dim3 attn_grid(SEQ / 64, BATCH * HEADS);
    attn_kernel<<<attn_grid, 256, ATTN_SMEM_BYTES>>>(gq, gk, gv, go);

    // output projection
    split_w_kernel<<<convW_blocks, 256>>>(Wo, gw2);
    split_a_kernel<<<convA_blocks, 256>>>(go, ga2);
    gemm_mma_kernel<<<gemm_grid, 256, GEMM_SMEM>>>(ga2, gw2, bo, out, DIM);
}

// round 4
// speedup vs baseline: 2.0775x; 1.5141x over previous
#include <cuda_runtime.h>
#include <cuda_bf16.h>
#include <math.h>
#include <stdint.h>

// Problem constants
#define BATCH 4
#define SEQ   2048
#define DIM   2048
#define HEADS 16
#define HDIM  128
#define MTOK  (BATCH * SEQ)          // 8192 tokens
#define NROWS_NORM (MTOK * HEADS)    // 131072 (token,head) rows of 128
#define KP    (3 * DIM)              // 6144 split-bf16 K'

// -------------------- scratch (device globals; no cudaMalloc allowed) ------
__device__ float g_q[(size_t)MTOK * DIM];
__device__ float g_k[(size_t)MTOK * DIM];
__device__ float g_v[(size_t)MTOK * DIM];
__device__ float g_o[(size_t)MTOK * DIM];
__device__ __align__(1024) __nv_bfloat16 g_a2[(size_t)MTOK * KP];  // split activations
__device__ __align__(1024) __nv_bfloat16 g_w2[(size_t)DIM * KP];   // split weights

// ===========================================================================
// helpers
// ===========================================================================
__device__ __forceinline__ uint32_t smem_u32(const void* p) {
    uint32_t a;
    asm("{ .reg .u64 t; cvta.to.shared.u64 t, %1; cvt.u32.u64 %0, t; }"
        : "=r"(a) : "l"(p));
    return a;
}

__device__ __forceinline__ void cp_async16(uint32_t saddr, const void* gptr) {
    asm volatile("cp.async.cg.shared.global [%0], [%1], 16;"
                 :: "r"(saddr), "l"(gptr) : "memory");
}

__device__ __forceinline__ void ldsm4(uint32_t& r0, uint32_t& r1,
                                      uint32_t& r2, uint32_t& r3, uint32_t addr) {
    asm volatile("ldmatrix.sync.aligned.m8n8.x4.shared.b16 {%0,%1,%2,%3}, [%4];"
                 : "=r"(r0), "=r"(r1), "=r"(r2), "=r"(r3) : "r"(addr));
}

__device__ __forceinline__ void ldsm4t(uint32_t& r0, uint32_t& r1,
                                       uint32_t& r2, uint32_t& r3, uint32_t addr) {
    asm volatile("ldmatrix.sync.aligned.m8n8.x4.trans.shared.b16 {%0,%1,%2,%3}, [%4];"
                 : "=r"(r0), "=r"(r1), "=r"(r2), "=r"(r3) : "r"(addr));
}

__device__ __forceinline__ void mma_bf16(float* c, const uint32_t* a,
                                         uint32_t b0, uint32_t b1) {
    asm volatile(
        "mma.sync.aligned.m16n8k16.row.col.f32.bf16.bf16.f32 "
        "{%0,%1,%2,%3}, {%4,%5,%6,%7}, {%8,%9}, {%0,%1,%2,%3};"
        : "+f"(c[0]), "+f"(c[1]), "+f"(c[2]), "+f"(c[3])
        : "r"(a[0]), "r"(a[1]), "r"(a[2]), "r"(a[3]), "r"(b0), "r"(b1));
}

// split x into bf16 hi + lo, packed pairwise
__device__ __forceinline__ void split2(float x, float y, uint32_t& hi, uint32_t& lo) {
    __nv_bfloat16 hx = __float2bfloat16(x);
    __nv_bfloat16 hy = __float2bfloat16(y);
    float lx = x - __bfloat162float(hx);
    float ly = y - __bfloat162float(hy);
    __nv_bfloat162 h2; h2.x = hx; h2.y = hy;
    __nv_bfloat162 l2 = __floats2bfloat162_rn(lx, ly);
    hi = *reinterpret_cast<uint32_t*>(&h2);
    lo = *reinterpret_cast<uint32_t*>(&l2);
}

// ===========================================================================
// split conversion kernels (GEMM operands): A'=[hi|hi|lo], W'=[hi|lo|hi]
// ===========================================================================
__global__ void __launch_bounds__(256)
split_a_kernel(const float* __restrict__ x, __nv_bfloat16* __restrict__ out)
{
    int idx = blockIdx.x * 256 + threadIdx.x;
    int m = idx / (DIM / 2);
    int k2 = idx % (DIM / 2);
    float2 v = *(const float2*)&x[(size_t)m * DIM + k2 * 2];
    uint32_t hi, lo;
    split2(v.x, v.y, hi, lo);
    uint32_t* row = (uint32_t*)&out[(size_t)m * KP];
    row[k2] = hi;
    row[DIM / 2 + k2] = hi;
    row[DIM + k2] = lo;
}

__global__ void __launch_bounds__(256)
split_w_kernel(const float* __restrict__ x, __nv_bfloat16* __restrict__ out)
{
    int idx = blockIdx.x * 256 + threadIdx.x;
    int m = idx / (DIM / 2);
    int k2 = idx % (DIM / 2);
    float2 v = *(const float2*)&x[(size_t)m * DIM + k2 * 2];
    uint32_t hi, lo;
    split2(v.x, v.y, hi, lo);
    uint32_t* row = (uint32_t*)&out[(size_t)m * KP];
    row[k2] = hi;
    row[DIM / 2 + k2] = lo;
    row[DIM + k2] = hi;
}

// ===========================================================================
// HMMA GEMM (unchanged from R3): C[M,N] = A'[M,K'] @ W'[N,K']^T + bias
// ===========================================================================
#define BK       64
#define PITCH    72
#define PITCHB   (PITCH * 2)
#define TILEAB   (128 * PITCHB)
#define STAGE_B  (2 * TILEAB)
#define STAGES   3
#define NCHUNK   (KP / BK)
#define GEMM_SMEM (STAGES * STAGE_B)

__global__ void __launch_bounds__(256, 1)
gemm_mma_kernel(const __nv_bfloat16* __restrict__ Ap,
                const __nv_bfloat16* __restrict__ Bp,
                const float* __restrict__ bias, float* __restrict__ C, int N)
{
    extern __shared__ __align__(1024) char smem[];
    const uint32_t sbase = smem_u32(smem);
    const int tid  = threadIdx.x;
    const int lane = tid & 31;
    const int wid  = tid >> 5;
    const int wm   = (wid >> 2) * 64;
    const int wn   = (wid & 3) * 32;
    const int m0   = blockIdx.y * 128;
    const int n0   = blockIdx.x * 128;

    const __nv_bfloat16* Abase = Ap + (size_t)m0 * KP;
    const __nv_bfloat16* Bbase = Bp + (size_t)n0 * KP;

    const int lrow = tid >> 1;
    const int lcol = (tid & 1) * 4;
    auto load_tile = [&](int s, int c) {
        const uint32_t sa = sbase + s * STAGE_B;
        const uint32_t sb = sa + TILEAB;
        const __nv_bfloat16* Ag = Abase + (size_t)lrow * KP + c * BK + lcol * 8;
        const __nv_bfloat16* Bg = Bbase + (size_t)lrow * KP + c * BK + lcol * 8;
        const uint32_t so = lrow * PITCHB + lcol * 16;
        #pragma unroll
        for (int i = 0; i < 4; i++) {
            cp_async16(sa + so + i * 16, Ag + i * 8);
            cp_async16(sb + so + i * 16, Bg + i * 8);
        }
        asm volatile("cp.async.commit_group;" ::: "memory");
    };

    float acc[4][4][4];
    #pragma unroll
    for (int mi = 0; mi < 4; mi++)
        #pragma unroll
        for (int ni = 0; ni < 4; ni++)
            #pragma unroll
            for (int r = 0; r < 4; r++) acc[mi][ni][r] = 0.f;

    load_tile(0, 0);
    load_tile(1, 1);

    const uint32_t arow = wm + (lane & 15);
    const uint32_t brow = wn + (lane & 15);
    const uint32_t koff = (lane >> 4) * 16;

    for (int c = 0; c < NCHUNK; c++) {
        const int s = c % STAGES;
        asm volatile("cp.async.wait_group 1;" ::: "memory");
        __syncthreads();

        const uint32_t sa = sbase + s * STAGE_B + arow * PITCHB + koff;
        const uint32_t sb = sbase + s * STAGE_B + TILEAB + brow * PITCHB + koff;

        #pragma unroll
        for (int ks = 0; ks < 4; ks++) {
            uint32_t a[4][4];
            #pragma unroll
            for (int mi = 0; mi < 4; mi++)
                ldsm4(a[mi][0], a[mi][1], a[mi][2], a[mi][3],
                      sa + mi * 16 * PITCHB + ks * 32);
            uint32_t b[2][4];
            #pragma unroll
            for (int nb = 0; nb < 2; nb++)
                ldsm4(b[nb][0], b[nb][1], b[nb][2], b[nb][3],
                      sb + nb * 16 * PITCHB + ks * 32);
            #pragma unroll
            for (int mi = 0; mi < 4; mi++)
                #pragma unroll
                for (int ni = 0; ni < 4; ni++)
                    mma_bf16(acc[mi][ni], a[mi],
                             b[ni >> 1][ni & 1], b[ni >> 1][(ni & 1) + 2]);
        }

        __syncthreads();
        const int y = c + 2;
        if (y < NCHUNK) load_tile(y % STAGES, y);
        else asm volatile("cp.async.commit_group;" ::: "memory");
    }

    #pragma unroll
    for (int mi = 0; mi < 4; mi++) {
        const int r = m0 + wm + mi * 16 + (lane >> 2);
        #pragma unroll
        for (int ni = 0; ni < 4; ni++) {
            const int col = n0 + wn + ni * 8 + (lane & 3) * 2;
            float2 v0, v1;
            v0.x = acc[mi][ni][0] + bias[col];
            v0.y = acc[mi][ni][1] + bias[col + 1];
            v1.x = acc[mi][ni][2] + bias[col];
            v1.y = acc[mi][ni][3] + bias[col + 1];
            *(float2*)&C[(size_t)r * N + col]       = v0;
            *(float2*)&C[(size_t)(r + 8) * N + col] = v1;
        }
    }
}

// ---------------------------------------------------------------------------
// RMSNorm over head_dim=128
// ---------------------------------------------------------------------------
__global__ void __launch_bounds__(256)
rmsnorm_kernel(float* __restrict__ x, const float* __restrict__ w, int nrows)
{
    int gwarp = (blockIdx.x * blockDim.x + threadIdx.x) >> 5;
    int lane  = threadIdx.x & 31;
    if (gwarp >= nrows) return;

    float4 v = *(float4*)&x[(size_t)gwarp * 128 + lane * 4];
    float ss = v.x * v.x + v.y * v.y + v.z * v.z + v.w * v.w;
#pragma unroll
    for (int off = 16; off >= 1; off >>= 1)
        ss += __shfl_xor_sync(0xffffffffu, ss, off);
    float r = rsqrtf(ss * (1.0f / 128.0f) + 1e-6f);
    float4 wv = *(const float4*)&w[lane * 4];
    v.x *= r * wv.x; v.y *= r * wv.y; v.z *= r * wv.z; v.w *= r * wv.w;
    *(float4*)&x[(size_t)gwarp * 128 + lane * 4] = v;
}

// ===========================================================================
// HMMA flash attention, 3-term split-bf16 precision.
// CTA = one (b,h), 128 q rows. KV streamed in 64-row tiles.
// 8 warps; warp w owns q rows 16w..16w+15.
// S = [qhi|qhi|qlo] . [khi|klo|khi]^T ; O += [phi|phi|plo] . [vhi|vlo|vhi]
// smem pitch 272B (17 mod 8 distinct -> conflict-free ldmatrix).
// ===========================================================================
#define QT   128
#define KT   64
#define APIT 272
#define QH_OFF 0
#define QL_OFF (QT * APIT)                    // 34816
#define KH_OFF (2 * QT * APIT)                // 69632
#define KL_OFF (KH_OFF + KT * APIT)           // 87040
#define VH_OFF (KL_OFF + KT * APIT)           // 104448
#define VL_OFF (VH_OFF + KT * APIT)           // 121856
#define ATTN_SMEM (VL_OFF + KT * APIT)        // 139264

__global__ void __launch_bounds__(256, 1)
attn_mma_kernel(const float* __restrict__ Qg, const float* __restrict__ Kg,
                const float* __restrict__ Vg, float* __restrict__ Og)
{
    extern __shared__ __align__(1024) char asmem[];
    char* sp = asmem;
    const uint32_t sb = smem_u32(asmem);

    const int tid  = threadIdx.x;
    const int lane = tid & 31;
    const int wid  = tid >> 5;
    const int wm   = wid * 16;                 // warp's q-row base within tile
    const int sq0  = blockIdx.x * QT;
    const int b    = blockIdx.y >> 4;
    const int h    = blockIdx.y & 15;
    const float scale = 0.08838834764831845f;  // 1/sqrt(128)

    const float* Qb = Qg + (size_t)(b * SEQ + sq0) * DIM + h * HDIM;
    const float* Kb = Kg + (size_t)b * SEQ * DIM + h * HDIM;
    const float* Vb = Vg + (size_t)b * SEQ * DIM + h * HDIM;

    // ---- stage Q (pre-scaled), split hi/lo: 128x128 = 4096 float4 ----
    #pragma unroll
    for (int i = 0; i < 16; i++) {
        int idx = tid + i * 256;
        int row = idx >> 5;
        int c4  = idx & 31;
        float4 v = *(const float4*)&Qb[(size_t)row * DIM + c4 * 4];
        v.x *= scale; v.y *= scale; v.z *= scale; v.w *= scale;
        uint32_t h01, l01, h23, l23;
        split2(v.x, v.y, h01, l01);
        split2(v.z, v.w, h23, l23);
        uint32_t off = row * APIT + c4 * 8;
        *(uint2*)(sp + QH_OFF + off) = make_uint2(h01, h23);
        *(uint2*)(sp + QL_OFF + off) = make_uint2(l01, l23);
    }

    // fragment state
    float Sf[8][4];
    float Of[16][4];
    #pragma unroll
    for (int j = 0; j < 16; j++)
        #pragma unroll
        for (int r = 0; r < 4; r++) Of[j][r] = 0.f;
    float m0 = -1e30f, m1 = -1e30f, l0 = 0.f, l1 = 0.f;

    // ldmatrix lane offsets
    const uint32_t qoff = (wm + (lane & 15)) * APIT + (lane >> 4) * 16;
    const uint32_t boff = ((lane & 7) + ((lane >> 4) << 3)) * APIT + ((lane >> 3) & 1) * 16;
    const uint32_t voff = ((lane & 7) + ((lane >> 3) & 1) * 8) * APIT + (lane >> 4) * 16;

    for (int kt = 0; kt < SEQ / KT; kt++) {
        __syncthreads();   // prior tile's smem reads complete (also covers Q staging)

        // ---- stage K,V tile (64x128), split hi/lo ----
        const float* Kt = Kb + (size_t)(kt * KT) * DIM;
        const float* Vt = Vb + (size_t)(kt * KT) * DIM;
        #pragma unroll
        for (int i = 0; i < 8; i++) {
            int idx = tid + i * 256;
            int row = idx >> 5;
            int c4  = idx & 31;
            uint32_t off = row * APIT + c4 * 8;
            float4 kv = *(const float4*)&Kt[(size_t)row * DIM + c4 * 4];
            uint32_t h01, l01, h23, l23;
            split2(kv.x, kv.y, h01, l01);
            split2(kv.z, kv.w, h23, l23);
            *(uint2*)(sp + KH_OFF + off) = make_uint2(h01, h23);
            *(uint2*)(sp + KL_OFF + off) = make_uint2(l01, l23);
            float4 vv = *(const float4*)&Vt[(size_t)row * DIM + c4 * 4];
            split2(vv.x, vv.y, h01, l01);
            split2(vv.z, vv.w, h23, l23);
            *(uint2*)(sp + VH_OFF + off) = make_uint2(h01, h23);
            *(uint2*)(sp + VL_OFF + off) = make_uint2(l01, l23);
        }
        __syncthreads();

        // ---- S = Q'.K'^T : 3 passes of k=128 ----
        #pragma unroll
        for (int j = 0; j < 8; j++)
            #pragma unroll
            for (int r = 0; r < 4; r++) Sf[j][r] = 0.f;

        #pragma unroll
        for (int pass = 0; pass < 3; pass++) {
            const uint32_t abase = sb + (pass < 2 ? QH_OFF : QL_OFF) + qoff;
            const uint32_t bbase = sb + (pass == 1 ? KL_OFF : KH_OFF) + boff;
            #pragma unroll
            for (int ks = 0; ks < 8; ks++) {
                uint32_t a[4];
                ldsm4(a[0], a[1], a[2], a[3], abase + ks * 32);
                #pragma unroll
                for (int g = 0; g < 4; g++) {
                    uint32_t r0, r1, r2, r3;
                    ldsm4(r0, r1, r2, r3, bbase + g * 16 * APIT + ks * 32);
                    mma_bf16(Sf[2 * g],     a, r0, r1);
                    mma_bf16(Sf[2 * g + 1], a, r2, r3);
                }
            }
        }

        // ---- online softmax (rows r=lane>>2 and r+8; quad = 4 lanes) ----
        float rmax0 = -1e30f, rmax1 = -1e30f;
        #pragma unroll
        for (int j = 0; j < 8; j++) {
            rmax0 = fmaxf(rmax0, fmaxf(Sf[j][0], Sf[j][1]));
            rmax1 = fmaxf(rmax1, fmaxf(Sf[j][2], Sf[j][3]));
        }
        rmax0 = fmaxf(rmax0, __shfl_xor_sync(0xffffffffu, rmax0, 1));
        rmax0 = fmaxf(rmax0, __shfl_xor_sync(0xffffffffu, rmax0, 2));
        rmax1 = fmaxf(rmax1, __shfl_xor_sync(0xffffffffu, rmax1, 1));
        rmax1 = fmaxf(rmax1, __shfl_xor_sync(0xffffffffu, rmax1, 2));

        float mn0 = fmaxf(m0, rmax0);
        float mn1 = fmaxf(m1, rmax1);
        float al0 = __expf(m0 - mn0);
        float al1 = __expf(m1 - mn1);
        m0 = mn0; m1 = mn1;

        float rs0 = 0.f, rs1 = 0.f;
        uint32_t ph[8][2], pl[8][2];
        #pragma unroll
        for (int j = 0; j < 8; j++) {
            float p0 = __expf(Sf[j][0] - m0);
            float p1 = __expf(Sf[j][1] - m0);
            float p2 = __expf(Sf[j][2] - m1);
            float p3 = __expf(Sf[j][3] - m1);
            rs0 += p0 + p1;
            rs1 += p2 + p3;
            split2(p0, p1, ph[j][0], pl[j][0]);
            split2(p2, p3, ph[j][1], pl[j][1]);
        }
        rs0 += __shfl_xor_sync(0xffffffffu, rs0, 1);
        rs0 += __shfl_xor_sync(0xffffffffu, rs0, 2);
        rs1 += __shfl_xor_sync(0xffffffffu, rs1, 1);
        rs1 += __shfl_xor_sync(0xffffffffu, rs1, 2);
        l0 = l0 * al0 + rs0;
        l1 = l1 * al1 + rs1;

        #pragma unroll
        for (int j = 0; j < 16; j++) {
            Of[j][0] *= al0; Of[j][1] *= al0;
            Of[j][2] *= al1; Of[j][3] *= al1;
        }

        // ---- O += P'.V' : 4 k-steps of 16 keys ----
        const uint32_t vhb = sb + VH_OFF + voff;
        const uint32_t vlb = sb + VL_OFF + voff;
        #pragma unroll
        for (int ks = 0; ks < 4; ks++) {
            uint32_t pa_h[4] = { ph[2 * ks][0], ph[2 * ks][1],
                                 ph[2 * ks + 1][0], ph[2 * ks + 1][1] };
            uint32_t pa_l[4] = { pl[2 * ks][0], pl[2 * ks][1],
                                 pl[2 * ks + 1][0], pl[2 * ks + 1][1] };
            #pragma unroll
            for (int g = 0; g < 8; g++) {
                uint32_t vh0, vh1, vh2, vh3, vl0, vl1, vl2, vl3;
                ldsm4t(vh0, vh1, vh2, vh3, vhb + ks * 16 * APIT + g * 32);
                ldsm4t(vl0, vl1, vl2, vl3, vlb + ks * 16 * APIT + g * 32);
                mma_bf16(Of[2 * g],     pa_h, vh0, vh1);
                mma_bf16(Of[2 * g + 1], pa_h, vh2, vh3);
                mma_bf16(Of[2 * g],     pa_h, vl0, vl1);
                mma_bf16(Of[2 * g + 1], pa_h, vl2, vl3);
                mma_bf16(Of[2 * g],     pa_l, vh0, vh1);
                mma_bf16(Of[2 * g + 1], pa_l, vh2, vh3);
            }
        }
    }

    // ---- normalize and store ----
    const float inv0 = 1.0f / l0;
    const float inv1 = 1.0f / l1;
    const int r  = lane >> 2;
    const int c2 = (lane & 3) * 2;
    float* Ob = Og + (size_t)(b * SEQ + sq0 + wm) * DIM + h * HDIM;
    #pragma unroll
    for (int j = 0; j < 16; j++) {
        const int col = j * 8 + c2;
        float2 v0, v1;
        v0.x = Of[j][0] * inv0; v0.y = Of[j][1] * inv0;
        v1.x = Of[j][2] * inv1; v1.y = Of[j][3] * inv1;
        *(float2*)&Ob[(size_t)r * DIM + col]       = v0;
        *(float2*)&Ob[(size_t)(r + 8) * DIM + col] = v1;
    }
}

// ---------------------------------------------------------------------------
extern "C" void kernel_launch(void* const* d_in, const int* in_sizes, int n_in,
                              void* d_out, int out_size)
{
    const float* query = (const float*)d_in[0];
    const float* key   = (const float*)d_in[1];
    const float* value = (const float*)d_in[2];
    const float* Wq    = (const float*)d_in[3];
    const float* bq    = (const float*)d_in[4];
    const float* Wk    = (const float*)d_in[5];
    const float* bk    = (const float*)d_in[6];
    const float* Wv    = (const float*)d_in[7];
    const float* bv    = (const float*)d_in[8];
    const float* Wo    = (const float*)d_in[9];
    const float* bo    = (const float*)d_in[10];
    const float* qnw   = (const float*)d_in[11];
    const float* knw   = (const float*)d_in[12];
    float* out = (float*)d_out;

    float *gq, *gk, *gv, *go;
    __nv_bfloat16 *ga2, *gw2;
    cudaGetSymbolAddress((void**)&gq, g_q);
    cudaGetSymbolAddress((void**)&gk, g_k);
    cudaGetSymbolAddress((void**)&gv, g_v);
    cudaGetSymbolAddress((void**)&go, g_o);
    cudaGetSymbolAddress((void**)&ga2, g_a2);
    cudaGetSymbolAddress((void**)&gw2, g_w2);

    cudaFuncSetAttribute(gemm_mma_kernel,
                         cudaFuncAttributeMaxDynamicSharedMemorySize, GEMM_SMEM);
    cudaFuncSetAttribute(attn_mma_kernel,
                         cudaFuncAttributeMaxDynamicSharedMemorySize, ATTN_SMEM);

    const int convA_blocks = MTOK * (DIM / 2) / 256;   // 32768
    const int convW_blocks = DIM * (DIM / 2) / 256;    // 8192
    dim3 gemm_grid(DIM / 128, MTOK / 128);             // (16, 64)

    // Q projection
    split_w_kernel<<<convW_blocks, 256>>>(Wq, gw2);
    split_a_kernel<<<convA_blocks, 256>>>(query, ga2);
    gemm_mma_kernel<<<gemm_grid, 256, GEMM_SMEM>>>(ga2, gw2, bq, gq, DIM);
    // K projection
    split_w_kernel<<<convW_blocks, 256>>>(Wk, gw2);
    split_a_kernel<<<convA_blocks, 256>>>(key, ga2);
    gemm_mma_kernel<<<gemm_grid, 256, GEMM_SMEM>>>(ga2, gw2, bk, gk, DIM);
    // V projection
    split_w_kernel<<<convW_blocks, 256>>>(Wv, gw2);
    split_a_kernel<<<convA_blocks, 256>>>(value, ga2);
    gemm_mma_kernel<<<gemm_grid, 256, GEMM_SMEM>>>(ga2, gw2, bv, gv, DIM);

    // per-head RMSNorm on q and k
    int norm_blocks = NROWS_NORM / 8;
    rmsnorm_kernel<<<norm_blocks, 256>>>(gq, qnw, NROWS_NORM);
    rmsnorm_kernel<<<norm_blocks, 256>>>(gk, knw, NROWS_NORM);

    // attention (HMMA, split-bf16)
    dim3 attn_grid(SEQ / QT, BATCH * HEADS);           // (16, 64)
    attn_mma_kernel<<<attn_grid, 256, ATTN_SMEM>>>(gq, gk, gv, go);

    // output projection
    split_w_kernel<<<convW_blocks, 256>>>(Wo, gw2);
    split_a_kernel<<<convA_blocks, 256>>>(go, ga2);
    gemm_mma_kernel<<<gemm_grid, 256, GEMM_SMEM>>>(ga2, gw2, bo, out, DIM);
}

// round 5
// speedup vs baseline: 3.1394x; 1.5111x over previous
#include <cuda_runtime.h>
#include <cuda_bf16.h>
#include <math.h>
#include <stdint.h>

// Problem constants
#define BATCH 4
#define SEQ   2048
#define DIM   2048
#define HEADS 16
#define HDIM  128
#define MTOK  (BATCH * SEQ)          // 8192 tokens
#define NROWS_NORM (MTOK * HEADS)    // 131072 (token,head) rows of 128

// -------------------- scratch (device globals; no cudaMalloc allowed) ------
__device__ float g_q[(size_t)MTOK * DIM];
__device__ float g_k[(size_t)MTOK * DIM];
__device__ float g_v[(size_t)MTOK * DIM];
__device__ float g_o[(size_t)MTOK * DIM];   // attention out, tf32-rounded
__device__ __align__(1024) float g_at[(size_t)MTOK * DIM];  // tf32 activations
__device__ __align__(1024) float g_wt[(size_t)DIM * DIM];   // tf32 weights

// ===========================================================================
// helpers
// ===========================================================================
__device__ __forceinline__ uint32_t smem_u32(const void* p) {
    uint32_t a;
    asm("{ .reg .u64 t; cvta.to.shared.u64 t, %1; cvt.u32.u64 %0, t; }"
        : "=r"(a) : "l"(p));
    return a;
}

__device__ __forceinline__ void cp_async16(uint32_t saddr, const void* gptr) {
    asm volatile("cp.async.cg.shared.global [%0], [%1], 16;"
                 :: "r"(saddr), "l"(gptr) : "memory");
}

__device__ __forceinline__ void ldsm4(uint32_t& r0, uint32_t& r1,
                                      uint32_t& r2, uint32_t& r3, uint32_t addr) {
    asm volatile("ldmatrix.sync.aligned.m8n8.x4.shared.b16 {%0,%1,%2,%3}, [%4];"
                 : "=r"(r0), "=r"(r1), "=r"(r2), "=r"(r3) : "r"(addr));
}

__device__ __forceinline__ void ldsm4t(uint32_t& r0, uint32_t& r1,
                                       uint32_t& r2, uint32_t& r3, uint32_t addr) {
    asm volatile("ldmatrix.sync.aligned.m8n8.x4.trans.shared.b16 {%0,%1,%2,%3}, [%4];"
                 : "=r"(r0), "=r"(r1), "=r"(r2), "=r"(r3) : "r"(addr));
}

__device__ __forceinline__ void mma_bf16(float* c, const uint32_t* a,
                                         uint32_t b0, uint32_t b1) {
    asm volatile(
        "mma.sync.aligned.m16n8k16.row.col.f32.bf16.bf16.f32 "
        "{%0,%1,%2,%3}, {%4,%5,%6,%7}, {%8,%9}, {%0,%1,%2,%3};"
        : "+f"(c[0]), "+f"(c[1]), "+f"(c[2]), "+f"(c[3])
        : "r"(a[0]), "r"(a[1]), "r"(a[2]), "r"(a[3]), "r"(b0), "r"(b1));
}

// tf32 mma: same fragment register layout as bf16 k16, 32-bit elements
__device__ __forceinline__ void mma_tf32(float* c, const uint32_t* a,
                                         uint32_t b0, uint32_t b1) {
    asm volatile(
        "mma.sync.aligned.m16n8k8.row.col.f32.tf32.tf32.f32 "
        "{%0,%1,%2,%3}, {%4,%5,%6,%7}, {%8,%9}, {%0,%1,%2,%3};"
        : "+f"(c[0]), "+f"(c[1]), "+f"(c[2]), "+f"(c[3])
        : "r"(a[0]), "r"(a[1]), "r"(a[2]), "r"(a[3]), "r"(b0), "r"(b1));
}

__device__ __forceinline__ float tf32_rna(float x) {
    uint32_t u;
    asm("cvt.rna.tf32.f32 %0, %1;" : "=r"(u) : "f"(x));
    return __uint_as_float(u);
}

// split x into bf16 hi + lo, packed pairwise (attention precision path)
__device__ __forceinline__ void split2(float x, float y, uint32_t& hi, uint32_t& lo) {
    __nv_bfloat16 hx = __float2bfloat16(x);
    __nv_bfloat16 hy = __float2bfloat16(y);
    float lx = x - __bfloat162float(hx);
    float ly = y - __bfloat162float(hy);
    __nv_bfloat162 h2; h2.x = hx; h2.y = hy;
    __nv_bfloat162 l2 = __floats2bfloat162_rn(lx, ly);
    hi = *reinterpret_cast<uint32_t*>(&h2);
    lo = *reinterpret_cast<uint32_t*>(&l2);
}

// ===========================================================================
// tf32 rounding copy (for GEMM operands)
// ===========================================================================
__global__ void __launch_bounds__(256)
tf32_round_kernel(const float* __restrict__ in, float* __restrict__ out)
{
    int i = blockIdx.x * 256 + threadIdx.x;
    float4 v = ((const float4*)in)[i];
    v.x = tf32_rna(v.x); v.y = tf32_rna(v.y);
    v.z = tf32_rna(v.z); v.w = tf32_rna(v.w);
    ((float4*)out)[i] = v;
}

// ===========================================================================
// TF32 HMMA GEMM: C[M,N] = A[M,K] @ W[N,K]^T + bias   (K = 2048, tf32)
// CTA 128x128, K-chunk = 64 floats (256B rows, pitch 272B), 3-stage cp.async.
// 8 warps (2x4), warp tile 64x32 via m16n8k8 tf32 atoms.
// ===========================================================================
#define GBK      64
#define GPITCHB  272
#define TILEAB   (128 * GPITCHB)               // 34816
#define STAGE_B  (2 * TILEAB)                  // 69632
#define STAGES   3
#define NCHUNK   (DIM / GBK)                   // 32
#define GEMM_SMEM (STAGES * STAGE_B)           // 208896

__global__ void __launch_bounds__(256, 1)
gemm_mma_kernel(const float* __restrict__ Ap, const float* __restrict__ Bp,
                const float* __restrict__ bias, float* __restrict__ C, int N)
{
    extern __shared__ __align__(1024) char smem[];
    const uint32_t sbase = smem_u32(smem);
    const int tid  = threadIdx.x;
    const int lane = tid & 31;
    const int wid  = tid >> 5;
    const int wm   = (wid >> 2) * 64;
    const int wn   = (wid & 3) * 32;
    const int m0   = blockIdx.y * 128;
    const int n0   = blockIdx.x * 128;

    const float* Abase = Ap + (size_t)m0 * DIM;
    const float* Bbase = Bp + (size_t)n0 * DIM;

    auto load_tile = [&](int s, int c) {
        const uint32_t sa = sbase + s * STAGE_B;
        const uint32_t sbuf = sa + TILEAB;
        #pragma unroll
        for (int i = 0; i < 8; i++) {
            int idx = tid + i * 256;
            int row = idx >> 4, seg = idx & 15;
            uint32_t so = row * GPITCHB + seg * 16;
            cp_async16(sa + so,   Abase + (size_t)row * DIM + c * GBK + seg * 4);
            cp_async16(sbuf + so, Bbase + (size_t)row * DIM + c * GBK + seg * 4);
        }
        asm volatile("cp.async.commit_group;" ::: "memory");
    };

    float acc[4][4][4];
    #pragma unroll
    for (int mi = 0; mi < 4; mi++)
        #pragma unroll
        for (int ni = 0; ni < 4; ni++)
            #pragma unroll
            for (int r = 0; r < 4; r++) acc[mi][ni][r] = 0.f;

    load_tile(0, 0);
    load_tile(1, 1);

    const uint32_t arow = wm + (lane & 15);
    const uint32_t brow = wn + (lane & 15);
    const uint32_t koff = (lane >> 4) * 16;

    for (int c = 0; c < NCHUNK; c++) {
        const int s = c % STAGES;
        asm volatile("cp.async.wait_group 1;" ::: "memory");
        __syncthreads();

        const uint32_t sa = sbase + s * STAGE_B + arow * GPITCHB + koff;
        const uint32_t sb = sbase + s * STAGE_B + TILEAB + brow * GPITCHB + koff;

        // 8 k-steps of tf32 k=8 (32B each)
        #pragma unroll
        for (int ks = 0; ks < 8; ks++) {
            uint32_t a[4][4];
            #pragma unroll
            for (int mi = 0; mi < 4; mi++)
                ldsm4(a[mi][0], a[mi][1], a[mi][2], a[mi][3],
                      sa + mi * 16 * GPITCHB + ks * 32);
            uint32_t b[2][4];
            #pragma unroll
            for (int nb = 0; nb < 2; nb++)
                ldsm4(b[nb][0], b[nb][1], b[nb][2], b[nb][3],
                      sb + nb * 16 * GPITCHB + ks * 32);
            #pragma unroll
            for (int mi = 0; mi < 4; mi++)
                #pragma unroll
                for (int ni = 0; ni < 4; ni++)
                    mma_tf32(acc[mi][ni], a[mi],
                             b[ni >> 1][ni & 1], b[ni >> 1][(ni & 1) + 2]);
        }

        __syncthreads();
        const int y = c + 2;
        if (y < NCHUNK) load_tile(y % STAGES, y);
        else asm volatile("cp.async.commit_group;" ::: "memory");
    }

    #pragma unroll
    for (int mi = 0; mi < 4; mi++) {
        const int r = m0 + wm + mi * 16 + (lane >> 2);
        #pragma unroll
        for (int ni = 0; ni < 4; ni++) {
            const int col = n0 + wn + ni * 8 + (lane & 3) * 2;
            float2 v0, v1;
            v0.x = acc[mi][ni][0] + bias[col];
            v0.y = acc[mi][ni][1] + bias[col + 1];
            v1.x = acc[mi][ni][2] + bias[col];
            v1.y = acc[mi][ni][3] + bias[col + 1];
            *(float2*)&C[(size_t)r * N + col]       = v0;
            *(float2*)&C[(size_t)(r + 8) * N + col] = v1;
        }
    }
}

// ---------------------------------------------------------------------------
// RMSNorm over head_dim=128
// ---------------------------------------------------------------------------
__global__ void __launch_bounds__(256)
rmsnorm_kernel(float* __restrict__ x, const float* __restrict__ w, int nrows)
{
    int gwarp = (blockIdx.x * blockDim.x + threadIdx.x) >> 5;
    int lane  = threadIdx.x & 31;
    if (gwarp >= nrows) return;

    float4 v = *(float4*)&x[(size_t)gwarp * 128 + lane * 4];
    float ss = v.x * v.x + v.y * v.y + v.z * v.z + v.w * v.w;
#pragma unroll
    for (int off = 16; off >= 1; off >>= 1)
        ss += __shfl_xor_sync(0xffffffffu, ss, off);
    float r = rsqrtf(ss * (1.0f / 128.0f) + 1e-6f);
    float4 wv = *(const float4*)&w[lane * 4];
    v.x *= r * wv.x; v.y *= r * wv.y; v.z *= r * wv.z; v.w *= r * wv.w;
    *(float4*)&x[(size_t)gwarp * 128 + lane * 4] = v;
}

// ===========================================================================
// HMMA flash attention, 3-term split-bf16 precision (unchanged from R4,
// except output store is tf32-rounded for the out-projection).
// ===========================================================================
#define QT   128
#define KT   64
#define APIT 272
#define QH_OFF 0
#define QL_OFF (QT * APIT)
#define KH_OFF (2 * QT * APIT)
#define KL_OFF (KH_OFF + KT * APIT)
#define VH_OFF (KL_OFF + KT * APIT)
#define VL_OFF (VH_OFF + KT * APIT)
#define ATTN_SMEM (VL_OFF + KT * APIT)        // 139264

__global__ void __launch_bounds__(256, 1)
attn_mma_kernel(const float* __restrict__ Qg, const float* __restrict__ Kg,
                const float* __restrict__ Vg, float* __restrict__ Og)
{
    extern __shared__ __align__(1024) char asmem[];
    char* sp = asmem;
    const uint32_t sb = smem_u32(asmem);

    const int tid  = threadIdx.x;
    const int lane = tid & 31;
    const int wid  = tid >> 5;
    const int wm   = wid * 16;
    const int sq0  = blockIdx.x * QT;
    const int b    = blockIdx.y >> 4;
    const int h    = blockIdx.y & 15;
    const float scale = 0.08838834764831845f;

    const float* Qb = Qg + (size_t)(b * SEQ + sq0) * DIM + h * HDIM;
    const float* Kb = Kg + (size_t)b * SEQ * DIM + h * HDIM;
    const float* Vb = Vg + (size_t)b * SEQ * DIM + h * HDIM;

    #pragma unroll
    for (int i = 0; i < 16; i++) {
        int idx = tid + i * 256;
        int row = idx >> 5;
        int c4  = idx & 31;
        float4 v = *(const float4*)&Qb[(size_t)row * DIM + c4 * 4];
        v.x *= scale; v.y *= scale; v.z *= scale; v.w *= scale;
        uint32_t h01, l01, h23, l23;
        split2(v.x, v.y, h01, l01);
        split2(v.z, v.w, h23, l23);
        uint32_t off = row * APIT + c4 * 8;
        *(uint2*)(sp + QH_OFF + off) = make_uint2(h01, h23);
        *(uint2*)(sp + QL_OFF + off) = make_uint2(l01, l23);
    }

    float Sf[8][4];
    float Of[16][4];
    #pragma unroll
    for (int j = 0; j < 16; j++)
        #pragma unroll
        for (int r = 0; r < 4; r++) Of[j][r] = 0.f;
    float m0 = -1e30f, m1 = -1e30f, l0 = 0.f, l1 = 0.f;

    const uint32_t qoff = (wm + (lane & 15)) * APIT + (lane >> 4) * 16;
    const uint32_t boff = ((lane & 7) + ((lane >> 4) << 3)) * APIT + ((lane >> 3) & 1) * 16;
    const uint32_t voff = ((lane & 7) + ((lane >> 3) & 1) * 8) * APIT + (lane >> 4) * 16;

    for (int kt = 0; kt < SEQ / KT; kt++) {
        __syncthreads();

        const float* Kt = Kb + (size_t)(kt * KT) * DIM;
        const float* Vt = Vb + (size_t)(kt * KT) * DIM;
        #pragma unroll
        for (int i = 0; i < 8; i++) {
            int idx = tid + i * 256;
            int row = idx >> 5;
            int c4  = idx & 31;
            uint32_t off = row * APIT + c4 * 8;
            float4 kv = *(const float4*)&Kt[(size_t)row * DIM + c4 * 4];
            uint32_t h01, l01, h23, l23;
            split2(kv.x, kv.y, h01, l01);
            split2(kv.z, kv.w, h23, l23);
            *(uint2*)(sp + KH_OFF + off) = make_uint2(h01, h23);
            *(uint2*)(sp + KL_OFF + off) = make_uint2(l01, l23);
            float4 vv = *(const float4*)&Vt[(size_t)row * DIM + c4 * 4];
            split2(vv.x, vv.y, h01, l01);
            split2(vv.z, vv.w, h23, l23);
            *(uint2*)(sp + VH_OFF + off) = make_uint2(h01, h23);
            *(uint2*)(sp + VL_OFF + off) = make_uint2(l01, l23);
        }
        __syncthreads();

        #pragma unroll
        for (int j = 0; j < 8; j++)
            #pragma unroll
            for (int r = 0; r < 4; r++) Sf[j][r] = 0.f;

        #pragma unroll
        for (int pass = 0; pass < 3; pass++) {
            const uint32_t abase = sb + (pass < 2 ? QH_OFF : QL_OFF) + qoff;
            const uint32_t bbase = sb + (pass == 1 ? KL_OFF : KH_OFF) + boff;
            #pragma unroll
            for (int ks = 0; ks < 8; ks++) {
                uint32_t a[4];
                ldsm4(a[0], a[1], a[2], a[3], abase + ks * 32);
                #pragma unroll
                for (int g = 0; g < 4; g++) {
                    uint32_t r0, r1, r2, r3;
                    ldsm4(r0, r1, r2, r3, bbase + g * 16 * APIT + ks * 32);
                    mma_bf16(Sf[2 * g],     a, r0, r1);
                    mma_bf16(Sf[2 * g + 1], a, r2, r3);
                }
            }
        }

        float rmax0 = -1e30f, rmax1 = -1e30f;
        #pragma unroll
        for (int j = 0; j < 8; j++) {
            rmax0 = fmaxf(rmax0, fmaxf(Sf[j][0], Sf[j][1]));
            rmax1 = fmaxf(rmax1, fmaxf(Sf[j][2], Sf[j][3]));
        }
        rmax0 = fmaxf(rmax0, __shfl_xor_sync(0xffffffffu, rmax0, 1));
        rmax0 = fmaxf(rmax0, __shfl_xor_sync(0xffffffffu, rmax0, 2));
        rmax1 = fmaxf(rmax1, __shfl_xor_sync(0xffffffffu, rmax1, 1));
        rmax1 = fmaxf(rmax1, __shfl_xor_sync(0xffffffffu, rmax1, 2));

        float mn0 = fmaxf(m0, rmax0);
        float mn1 = fmaxf(m1, rmax1);
        float al0 = __expf(m0 - mn0);
        float al1 = __expf(m1 - mn1);
        m0 = mn0; m1 = mn1;

        float rs0 = 0.f, rs1 = 0.f;
        uint32_t ph[8][2], pl[8][2];
        #pragma unroll
        for (int j = 0; j < 8; j++) {
            float p0 = __expf(Sf[j][0] - m0);
            float p1 = __expf(Sf[j][1] - m0);
            float p2 = __expf(Sf[j][2] - m1);
            float p3 = __expf(Sf[j][3] - m1);
            rs0 += p0 + p1;
            rs1 += p2 + p3;
            split2(p0, p1, ph[j][0], pl[j][0]);
            split2(p2, p3, ph[j][1], pl[j][1]);
        }
        rs0 += __shfl_xor_sync(0xffffffffu, rs0, 1);
        rs0 += __shfl_xor_sync(0xffffffffu, rs0, 2);
        rs1 += __shfl_xor_sync(0xffffffffu, rs1, 1);
        rs1 += __shfl_xor_sync(0xffffffffu, rs1, 2);
        l0 = l0 * al0 + rs0;
        l1 = l1 * al1 + rs1;

        #pragma unroll
        for (int j = 0; j < 16; j++) {
            Of[j][0] *= al0; Of[j][1] *= al0;
            Of[j][2] *= al1; Of[j][3] *= al1;
        }

        const uint32_t vhb = sb + VH_OFF + voff;
        const uint32_t vlb = sb + VL_OFF + voff;
        #pragma unroll
        for (int ks = 0; ks < 4; ks++) {
            uint32_t pa_h[4] = { ph[2 * ks][0], ph[2 * ks][1],
                                 ph[2 * ks + 1][0], ph[2 * ks + 1][1] };
            uint32_t pa_l[4] = { pl[2 * ks][0], pl[2 * ks][1],
                                 pl[2 * ks + 1][0], pl[2 * ks + 1][1] };
            #pragma unroll
            for (int g = 0; g < 8; g++) {
                uint32_t vh0, vh1, vh2, vh3, vl0, vl1, vl2, vl3;
                ldsm4t(vh0, vh1, vh2, vh3, vhb + ks * 16 * APIT + g * 32);
                ldsm4t(vl0, vl1, vl2, vl3, vlb + ks * 16 * APIT + g * 32);
                mma_bf16(Of[2 * g],     pa_h, vh0, vh1);
                mma_bf16(Of[2 * g + 1], pa_h, vh2, vh3);
                mma_bf16(Of[2 * g],     pa_h, vl0, vl1);
                mma_bf16(Of[2 * g + 1], pa_h, vl2, vl3);
                mma_bf16(Of[2 * g],     pa_l, vh0, vh1);
                mma_bf16(Of[2 * g + 1], pa_l, vh2, vh3);
            }
        }
    }

    const float inv0 = 1.0f / l0;
    const float inv1 = 1.0f / l1;
    const int r  = lane >> 2;
    const int c2 = (lane & 3) * 2;
    float* Ob = Og + (size_t)(b * SEQ + sq0 + wm) * DIM + h * HDIM;
    #pragma unroll
    for (int j = 0; j < 16; j++) {
        const int col = j * 8 + c2;
        float2 v0, v1;
        v0.x = tf32_rna(Of[j][0] * inv0); v0.y = tf32_rna(Of[j][1] * inv0);
        v1.x = tf32_rna(Of[j][2] * inv1); v1.y = tf32_rna(Of[j][3] * inv1);
        *(float2*)&Ob[(size_t)r * DIM + col]       = v0;
        *(float2*)&Ob[(size_t)(r + 8) * DIM + col] = v1;
    }
}

// ---------------------------------------------------------------------------
extern "C" void kernel_launch(void* const* d_in, const int* in_sizes, int n_in,
                              void* d_out, int out_size)
{
    const float* query = (const float*)d_in[0];
    const float* key   = (const float*)d_in[1];
    const float* value = (const float*)d_in[2];
    const float* Wq    = (const float*)d_in[3];
    const float* bq    = (const float*)d_in[4];
    const float* Wk    = (const float*)d_in[5];
    const float* bk    = (const float*)d_in[6];
    const float* Wv    = (const float*)d_in[7];
    const float* bv    = (const float*)d_in[8];
    const float* Wo    = (const float*)d_in[9];
    const float* bo    = (const float*)d_in[10];
    const float* qnw   = (const float*)d_in[11];
    const float* knw   = (const float*)d_in[12];
    float* out = (float*)d_out;

    float *gq, *gk, *gv, *go, *gat, *gwt;
    cudaGetSymbolAddress((void**)&gq, g_q);
    cudaGetSymbolAddress((void**)&gk, g_k);
    cudaGetSymbolAddress((void**)&gv, g_v);
    cudaGetSymbolAddress((void**)&go, g_o);
    cudaGetSymbolAddress((void**)&gat, g_at);
    cudaGetSymbolAddress((void**)&gwt, g_wt);

    cudaFuncSetAttribute(gemm_mma_kernel,
                         cudaFuncAttributeMaxDynamicSharedMemorySize, GEMM_SMEM);
    cudaFuncSetAttribute(attn_mma_kernel,
                         cudaFuncAttributeMaxDynamicSharedMemorySize, ATTN_SMEM);

    const int convA_blocks = (MTOK * DIM / 4) / 256;   // 16384
    const int convW_blocks = (DIM * DIM / 4) / 256;    // 4096
    dim3 gemm_grid(DIM / 128, MTOK / 128);             // (16, 64)

    // Q projection
    tf32_round_kernel<<<convW_blocks, 256>>>(Wq, gwt);
    tf32_round_kernel<<<convA_blocks, 256>>>(query, gat);
    gemm_mma_kernel<<<gemm_grid, 256, GEMM_SMEM>>>(gat, gwt, bq, gq, DIM);
    // K projection
    tf32_round_kernel<<<convW_blocks, 256>>>(Wk, gwt);
    tf32_round_kernel<<<convA_blocks, 256>>>(key, gat);
    gemm_mma_kernel<<<gemm_grid, 256, GEMM_SMEM>>>(gat, gwt, bk, gk, DIM);
    // V projection
    tf32_round_kernel<<<convW_blocks, 256>>>(Wv, gwt);
    tf32_round_kernel<<<convA_blocks, 256>>>(value, gat);
    gemm_mma_kernel<<<gemm_grid, 256, GEMM_SMEM>>>(gat, gwt, bv, gv, DIM);

    // per-head RMSNorm on q and k
    int norm_blocks = NROWS_NORM / 8;
    rmsnorm_kernel<<<norm_blocks, 256>>>(gq, qnw, NROWS_NORM);
    rmsnorm_kernel<<<norm_blocks, 256>>>(gk, knw, NROWS_NORM);

    // attention (HMMA, split-bf16); writes tf32-rounded output
    dim3 attn_grid(SEQ / QT, BATCH * HEADS);           // (16, 64)
    attn_mma_kernel<<<attn_grid, 256, ATTN_SMEM>>>(gq, gk, gv, go);

    // output projection (g_o already tf32-rounded)
    tf32_round_kernel<<<convW_blocks, 256>>>(Wo, gwt);
    gemm_mma_kernel<<<gemm_grid, 256, GEMM_SMEM>>>(go, gwt, bo, out, DIM);
}

// round 6
// speedup vs baseline: 3.9929x; 1.2719x over previous
#include <cuda_runtime.h>
#include <cuda_bf16.h>
#include <cuda_fp16.h>
#include <math.h>
#include <stdint.h>

// Problem constants
#define BATCH 4
#define SEQ   2048
#define DIM   2048
#define HEADS 16
#define HDIM  128
#define MTOK  (BATCH * SEQ)          // 8192 tokens
#define NROWS_NORM (MTOK * HEADS)    // 131072 (token,head) rows of 128

// -------------------- scratch (device globals; no cudaMalloc allowed) ------
__device__ float g_q[(size_t)MTOK * DIM];
__device__ float g_k[(size_t)MTOK * DIM];
__device__ float g_v[(size_t)MTOK * DIM];
__device__ __align__(1024) __half g_a16[(size_t)MTOK * DIM];  // fp16 activations
__device__ __align__(1024) __half g_w16[(size_t)DIM * DIM];   // fp16 weights

// ===========================================================================
// helpers
// ===========================================================================
__device__ __forceinline__ uint32_t smem_u32(const void* p) {
    uint32_t a;
    asm("{ .reg .u64 t; cvta.to.shared.u64 t, %1; cvt.u32.u64 %0, t; }"
        : "=r"(a) : "l"(p));
    return a;
}

__device__ __forceinline__ void cp_async16(uint32_t saddr, const void* gptr) {
    asm volatile("cp.async.cg.shared.global [%0], [%1], 16;"
                 :: "r"(saddr), "l"(gptr) : "memory");
}

__device__ __forceinline__ void ldsm4(uint32_t& r0, uint32_t& r1,
                                      uint32_t& r2, uint32_t& r3, uint32_t addr) {
    asm volatile("ldmatrix.sync.aligned.m8n8.x4.shared.b16 {%0,%1,%2,%3}, [%4];"
                 : "=r"(r0), "=r"(r1), "=r"(r2), "=r"(r3) : "r"(addr));
}

__device__ __forceinline__ void ldsm4t(uint32_t& r0, uint32_t& r1,
                                       uint32_t& r2, uint32_t& r3, uint32_t addr) {
    asm volatile("ldmatrix.sync.aligned.m8n8.x4.trans.shared.b16 {%0,%1,%2,%3}, [%4];"
                 : "=r"(r0), "=r"(r1), "=r"(r2), "=r"(r3) : "r"(addr));
}

__device__ __forceinline__ void mma_bf16(float* c, const uint32_t* a,
                                         uint32_t b0, uint32_t b1) {
    asm volatile(
        "mma.sync.aligned.m16n8k16.row.col.f32.bf16.bf16.f32 "
        "{%0,%1,%2,%3}, {%4,%5,%6,%7}, {%8,%9}, {%0,%1,%2,%3};"
        : "+f"(c[0]), "+f"(c[1]), "+f"(c[2]), "+f"(c[3])
        : "r"(a[0]), "r"(a[1]), "r"(a[2]), "r"(a[3]), "r"(b0), "r"(b1));
}

__device__ __forceinline__ void mma_fp16(float* c, const uint32_t* a,
                                         uint32_t b0, uint32_t b1) {
    asm volatile(
        "mma.sync.aligned.m16n8k16.row.col.f32.f16.f16.f32 "
        "{%0,%1,%2,%3}, {%4,%5,%6,%7}, {%8,%9}, {%0,%1,%2,%3};"
        : "+f"(c[0]), "+f"(c[1]), "+f"(c[2]), "+f"(c[3])
        : "r"(a[0]), "r"(a[1]), "r"(a[2]), "r"(a[3]), "r"(b0), "r"(b1));
}

// split x into bf16 hi + lo, packed pairwise (attention precision path)
__device__ __forceinline__ void split2(float x, float y, uint32_t& hi, uint32_t& lo) {
    __nv_bfloat16 hx = __float2bfloat16(x);
    __nv_bfloat16 hy = __float2bfloat16(y);
    float lx = x - __bfloat162float(hx);
    float ly = y - __bfloat162float(hy);
    __nv_bfloat162 h2; h2.x = hx; h2.y = hy;
    __nv_bfloat162 l2 = __floats2bfloat162_rn(lx, ly);
    hi = *reinterpret_cast<uint32_t*>(&h2);
    lo = *reinterpret_cast<uint32_t*>(&l2);
}

// ===========================================================================
// fp32 -> fp16 conversion (GEMM operands)
// ===========================================================================
__global__ void __launch_bounds__(256)
f2h_kernel(const float* __restrict__ in, __half* __restrict__ out)
{
    int i = blockIdx.x * 256 + threadIdx.x;
    float4 v = ((const float4*)in)[i];
    __half2 a = __floats2half2_rn(v.x, v.y);
    __half2 b = __floats2half2_rn(v.z, v.w);
    ((__half2*)out)[2 * i]     = a;
    ((__half2*)out)[2 * i + 1] = b;
}

// ===========================================================================
// fp16 HMMA GEMM: C[M,N] = A[M,K] @ W[N,K]^T + bias   (K=2048)
// CTA 128x128, BK=64, 3-stage cp.async pipeline, 8 warps (2x4), warp 64x32.
// smem pitch 72 halves (144B) -> conflict-free STS.128 and ldmatrix.
// (Structure identical to the R3 bf16 kernel, which measured at pipe rate.)
// ===========================================================================
#define BK       64
#define PITCHB   144
#define TILEAB   (128 * PITCHB)               // 18432 B per operand tile
#define STAGE_B  (2 * TILEAB)                 // 36864 B per stage
#define STAGES   3
#define NCHUNK   (DIM / BK)                   // 32
#define GEMM_SMEM (STAGES * STAGE_B)          // 110592 B

__global__ void __launch_bounds__(256, 1)
gemm_mma_kernel(const __half* __restrict__ Ap, const __half* __restrict__ Bp,
                const float* __restrict__ bias, float* __restrict__ C, int N)
{
    extern __shared__ __align__(1024) char smem[];
    const uint32_t sbase = smem_u32(smem);
    const int tid  = threadIdx.x;
    const int lane = tid & 31;
    const int wid  = tid >> 5;
    const int wm   = (wid >> 2) * 64;
    const int wn   = (wid & 3) * 32;
    const int m0   = blockIdx.y * 128;
    const int n0   = blockIdx.x * 128;

    const __half* Abase = Ap + (size_t)m0 * DIM;
    const __half* Bbase = Bp + (size_t)n0 * DIM;

    const int lrow = tid >> 1;
    const int lcol = (tid & 1) * 4;
    auto load_tile = [&](int s, int c) {
        const uint32_t sa = sbase + s * STAGE_B;
        const uint32_t sb = sa + TILEAB;
        const __half* Ag = Abase + (size_t)lrow * DIM + c * BK + lcol * 8;
        const __half* Bg = Bbase + (size_t)lrow * DIM + c * BK + lcol * 8;
        const uint32_t so = lrow * PITCHB + lcol * 16;
        #pragma unroll
        for (int i = 0; i < 4; i++) {
            cp_async16(sa + so + i * 16, Ag + i * 8);
            cp_async16(sb + so + i * 16, Bg + i * 8);
        }
        asm volatile("cp.async.commit_group;" ::: "memory");
    };

    float acc[4][4][4];
    #pragma unroll
    for (int mi = 0; mi < 4; mi++)
        #pragma unroll
        for (int ni = 0; ni < 4; ni++)
            #pragma unroll
            for (int r = 0; r < 4; r++) acc[mi][ni][r] = 0.f;

    load_tile(0, 0);
    load_tile(1, 1);

    const uint32_t arow = wm + (lane & 15);
    const uint32_t brow = wn + (lane & 15);
    const uint32_t koff = (lane >> 4) * 16;

    for (int c = 0; c < NCHUNK; c++) {
        const int s = c % STAGES;
        asm volatile("cp.async.wait_group 1;" ::: "memory");
        __syncthreads();

        const uint32_t sa = sbase + s * STAGE_B + arow * PITCHB + koff;
        const uint32_t sb = sbase + s * STAGE_B + TILEAB + brow * PITCHB + koff;

        #pragma unroll
        for (int ks = 0; ks < 4; ks++) {
            uint32_t a[4][4];
            #pragma unroll
            for (int mi = 0; mi < 4; mi++)
                ldsm4(a[mi][0], a[mi][1], a[mi][2], a[mi][3],
                      sa + mi * 16 * PITCHB + ks * 32);
            uint32_t b[2][4];
            #pragma unroll
            for (int nb = 0; nb < 2; nb++)
                ldsm4(b[nb][0], b[nb][1], b[nb][2], b[nb][3],
                      sb + nb * 16 * PITCHB + ks * 32);
            #pragma unroll
            for (int mi = 0; mi < 4; mi++)
                #pragma unroll
                for (int ni = 0; ni < 4; ni++)
                    mma_fp16(acc[mi][ni], a[mi],
                             b[ni >> 1][ni & 1], b[ni >> 1][(ni & 1) + 2]);
        }

        __syncthreads();
        const int y = c + 2;
        if (y < NCHUNK) load_tile(y % STAGES, y);
        else asm volatile("cp.async.commit_group;" ::: "memory");
    }

    #pragma unroll
    for (int mi = 0; mi < 4; mi++) {
        const int r = m0 + wm + mi * 16 + (lane >> 2);
        #pragma unroll
        for (int ni = 0; ni < 4; ni++) {
            const int col = n0 + wn + ni * 8 + (lane & 3) * 2;
            float2 v0, v1;
            v0.x = acc[mi][ni][0] + bias[col];
            v0.y = acc[mi][ni][1] + bias[col + 1];
            v1.x = acc[mi][ni][2] + bias[col];
            v1.y = acc[mi][ni][3] + bias[col + 1];
            *(float2*)&C[(size_t)r * N + col]       = v0;
            *(float2*)&C[(size_t)(r + 8) * N + col] = v1;
        }
    }
}

// ---------------------------------------------------------------------------
// RMSNorm over head_dim=128
// ---------------------------------------------------------------------------
__global__ void __launch_bounds__(256)
rmsnorm_kernel(float* __restrict__ x, const float* __restrict__ w, int nrows)
{
    int gwarp = (blockIdx.x * blockDim.x + threadIdx.x) >> 5;
    int lane  = threadIdx.x & 31;
    if (gwarp >= nrows) return;

    float4 v = *(float4*)&x[(size_t)gwarp * 128 + lane * 4];
    float ss = v.x * v.x + v.y * v.y + v.z * v.z + v.w * v.w;
#pragma unroll
    for (int off = 16; off >= 1; off >>= 1)
        ss += __shfl_xor_sync(0xffffffffu, ss, off);
    float r = rsqrtf(ss * (1.0f / 128.0f) + 1e-6f);
    float4 wv = *(const float4*)&w[lane * 4];
    v.x *= r * wv.x; v.y *= r * wv.y; v.z *= r * wv.z; v.w *= r * wv.w;
    *(float4*)&x[(size_t)gwarp * 128 + lane * 4] = v;
}

// ===========================================================================
// HMMA flash attention, 3-term split-bf16 precision.
// Output written as fp16 directly into the out-projection activation buffer.
// ===========================================================================
#define QT   128
#define KT   64
#define APIT 272
#define QH_OFF 0
#define QL_OFF (QT * APIT)
#define KH_OFF (2 * QT * APIT)
#define KL_OFF (KH_OFF + KT * APIT)
#define VH_OFF (KL_OFF + KT * APIT)
#define VL_OFF (VH_OFF + KT * APIT)
#define ATTN_SMEM (VL_OFF + KT * APIT)        // 139264

__global__ void __launch_bounds__(256, 1)
attn_mma_kernel(const float* __restrict__ Qg, const float* __restrict__ Kg,
                const float* __restrict__ Vg, __half* __restrict__ Og)
{
    extern __shared__ __align__(1024) char asmem[];
    char* sp = asmem;
    const uint32_t sb = smem_u32(asmem);

    const int tid  = threadIdx.x;
    const int lane = tid & 31;
    const int wid  = tid >> 5;
    const int wm   = wid * 16;
    const int sq0  = blockIdx.x * QT;
    const int b    = blockIdx.y >> 4;
    const int h    = blockIdx.y & 15;
    const float scale = 0.08838834764831845f;

    const float* Qb = Qg + (size_t)(b * SEQ + sq0) * DIM + h * HDIM;
    const float* Kb = Kg + (size_t)b * SEQ * DIM + h * HDIM;
    const float* Vb = Vg + (size_t)b * SEQ * DIM + h * HDIM;

    #pragma unroll
    for (int i = 0; i < 16; i++) {
        int idx = tid + i * 256;
        int row = idx >> 5;
        int c4  = idx & 31;
        float4 v = *(const float4*)&Qb[(size_t)row * DIM + c4 * 4];
        v.x *= scale; v.y *= scale; v.z *= scale; v.w *= scale;
        uint32_t h01, l01, h23, l23;
        split2(v.x, v.y, h01, l01);
        split2(v.z, v.w, h23, l23);
        uint32_t off = row * APIT + c4 * 8;
        *(uint2*)(sp + QH_OFF + off) = make_uint2(h01, h23);
        *(uint2*)(sp + QL_OFF + off) = make_uint2(l01, l23);
    }

    float Sf[8][4];
    float Of[16][4];
    #pragma unroll
    for (int j = 0; j < 16; j++)
        #pragma unroll
        for (int r = 0; r < 4; r++) Of[j][r] = 0.f;
    float m0 = -1e30f, m1 = -1e30f, l0 = 0.f, l1 = 0.f;

    const uint32_t qoff = (wm + (lane & 15)) * APIT + (lane >> 4) * 16;
    const uint32_t boff = ((lane & 7) + ((lane >> 4) << 3)) * APIT + ((lane >> 3) & 1) * 16;
    const uint32_t voff = ((lane & 7) + ((lane >> 3) & 1) * 8) * APIT + (lane >> 4) * 16;

    for (int kt = 0; kt < SEQ / KT; kt++) {
        __syncthreads();

        const float* Kt = Kb + (size_t)(kt * KT) * DIM;
        const float* Vt = Vb + (size_t)(kt * KT) * DIM;
        #pragma unroll
        for (int i = 0; i < 8; i++) {
            int idx = tid + i * 256;
            int row = idx >> 5;
            int c4  = idx & 31;
            uint32_t off = row * APIT + c4 * 8;
            float4 kv = *(const float4*)&Kt[(size_t)row * DIM + c4 * 4];
            uint32_t h01, l01, h23, l23;
            split2(kv.x, kv.y, h01, l01);
            split2(kv.z, kv.w, h23, l23);
            *(uint2*)(sp + KH_OFF + off) = make_uint2(h01, h23);
            *(uint2*)(sp + KL_OFF + off) = make_uint2(l01, l23);
            float4 vv = *(const float4*)&Vt[(size_t)row * DIM + c4 * 4];
            split2(vv.x, vv.y, h01, l01);
            split2(vv.z, vv.w, h23, l23);
            *(uint2*)(sp + VH_OFF + off) = make_uint2(h01, h23);
            *(uint2*)(sp + VL_OFF + off) = make_uint2(l01, l23);
        }
        __syncthreads();

        #pragma unroll
        for (int j = 0; j < 8; j++)
            #pragma unroll
            for (int r = 0; r < 4; r++) Sf[j][r] = 0.f;

        #pragma unroll
        for (int pass = 0; pass < 3; pass++) {
            const uint32_t abase = sb + (pass < 2 ? QH_OFF : QL_OFF) + qoff;
            const uint32_t bbase = sb + (pass == 1 ? KL_OFF : KH_OFF) + boff;
            #pragma unroll
            for (int ks = 0; ks < 8; ks++) {
                uint32_t a[4];
                ldsm4(a[0], a[1], a[2], a[3], abase + ks * 32);
                #pragma unroll
                for (int g = 0; g < 4; g++) {
                    uint32_t r0, r1, r2, r3;
                    ldsm4(r0, r1, r2, r3, bbase + g * 16 * APIT + ks * 32);
                    mma_bf16(Sf[2 * g],     a, r0, r1);
                    mma_bf16(Sf[2 * g + 1], a, r2, r3);
                }
            }
        }

        float rmax0 = -1e30f, rmax1 = -1e30f;
        #pragma unroll
        for (int j = 0; j < 8; j++) {
            rmax0 = fmaxf(rmax0, fmaxf(Sf[j][0], Sf[j][1]));
            rmax1 = fmaxf(rmax1, fmaxf(Sf[j][2], Sf[j][3]));
        }
        rmax0 = fmaxf(rmax0, __shfl_xor_sync(0xffffffffu, rmax0, 1));
        rmax0 = fmaxf(rmax0, __shfl_xor_sync(0xffffffffu, rmax0, 2));
        rmax1 = fmaxf(rmax1, __shfl_xor_sync(0xffffffffu, rmax1, 1));
        rmax1 = fmaxf(rmax1, __shfl_xor_sync(0xffffffffu, rmax1, 2));

        float mn0 = fmaxf(m0, rmax0);
        float mn1 = fmaxf(m1, rmax1);
        float al0 = __expf(m0 - mn0);
        float al1 = __expf(m1 - mn1);
        m0 = mn0; m1 = mn1;

        float rs0 = 0.f, rs1 = 0.f;
        uint32_t ph[8][2], pl[8][2];
        #pragma unroll
        for (int j = 0; j < 8; j++) {
            float p0 = __expf(Sf[j][0] - m0);
            float p1 = __expf(Sf[j][1] - m0);
            float p2 = __expf(Sf[j][2] - m1);
            float p3 = __expf(Sf[j][3] - m1);
            rs0 += p0 + p1;
            rs1 += p2 + p3;
            split2(p0, p1, ph[j][0], pl[j][0]);
            split2(p2, p3, ph[j][1], pl[j][1]);
        }
        rs0 += __shfl_xor_sync(0xffffffffu, rs0, 1);
        rs0 += __shfl_xor_sync(0xffffffffu, rs0, 2);
        rs1 += __shfl_xor_sync(0xffffffffu, rs1, 1);
        rs1 += __shfl_xor_sync(0xffffffffu, rs1, 2);
        l0 = l0 * al0 + rs0;
        l1 = l1 * al1 + rs1;

        #pragma unroll
        for (int j = 0; j < 16; j++) {
            Of[j][0] *= al0; Of[j][1] *= al0;
            Of[j][2] *= al1; Of[j][3] *= al1;
        }

        const uint32_t vhb = sb + VH_OFF + voff;
        const uint32_t vlb = sb + VL_OFF + voff;
        #pragma unroll
        for (int ks = 0; ks < 4; ks++) {
            uint32_t pa_h[4] = { ph[2 * ks][0], ph[2 * ks][1],
                                 ph[2 * ks + 1][0], ph[2 * ks + 1][1] };
            uint32_t pa_l[4] = { pl[2 * ks][0], pl[2 * ks][1],
                                 pl[2 * ks + 1][0], pl[2 * ks + 1][1] };
            #pragma unroll
            for (int g = 0; g < 8; g++) {
                uint32_t vh0, vh1, vh2, vh3, vl0, vl1, vl2, vl3;
                ldsm4t(vh0, vh1, vh2, vh3, vhb + ks * 16 * APIT + g * 32);
                ldsm4t(vl0, vl1, vl2, vl3, vlb + ks * 16 * APIT + g * 32);
                mma_bf16(Of[2 * g],     pa_h, vh0, vh1);
                mma_bf16(Of[2 * g + 1], pa_h, vh2, vh3);
                mma_bf16(Of[2 * g],     pa_h, vl0, vl1);
                mma_bf16(Of[2 * g + 1], pa_h, vl2, vl3);
                mma_bf16(Of[2 * g],     pa_l, vh0, vh1);
                mma_bf16(Of[2 * g + 1], pa_l, vh2, vh3);
            }
        }
    }

    // ---- normalize and store as fp16 (out-projection activation) ----
    const float inv0 = 1.0f / l0;
    const float inv1 = 1.0f / l1;
    const int r  = lane >> 2;
    const int c2 = (lane & 3) * 2;
    __half* Ob = Og + (size_t)(b * SEQ + sq0 + wm) * DIM + h * HDIM;
    #pragma unroll
    for (int j = 0; j < 16; j++) {
        const int col = j * 8 + c2;
        __half2 v0 = __floats2half2_rn(Of[j][0] * inv0, Of[j][1] * inv0);
        __half2 v1 = __floats2half2_rn(Of[j][2] * inv1, Of[j][3] * inv1);
        *(__half2*)&Ob[(size_t)r * DIM + col]       = v0;
        *(__half2*)&Ob[(size_t)(r + 8) * DIM + col] = v1;
    }
}

// ---------------------------------------------------------------------------
extern "C" void kernel_launch(void* const* d_in, const int* in_sizes, int n_in,
                              void* d_out, int out_size)
{
    const float* query = (const float*)d_in[0];
    const float* key   = (const float*)d_in[1];
    const float* value = (const float*)d_in[2];
    const float* Wq    = (const float*)d_in[3];
    const float* bq    = (const float*)d_in[4];
    const float* Wk    = (const float*)d_in[5];
    const float* bk    = (const float*)d_in[6];
    const float* Wv    = (const float*)d_in[7];
    const float* bv    = (const float*)d_in[8];
    const float* Wo    = (const float*)d_in[9];
    const float* bo    = (const float*)d_in[10];
    const float* qnw   = (const float*)d_in[11];
    const float* knw   = (const float*)d_in[12];
    float* out = (float*)d_out;

    float *gq, *gk, *gv;
    __half *ga16, *gw16;
    cudaGetSymbolAddress((void**)&gq, g_q);
    cudaGetSymbolAddress((void**)&gk, g_k);
    cudaGetSymbolAddress((void**)&gv, g_v);
    cudaGetSymbolAddress((void**)&ga16, g_a16);
    cudaGetSymbolAddress((void**)&gw16, g_w16);

    cudaFuncSetAttribute(gemm_mma_kernel,
                         cudaFuncAttributeMaxDynamicSharedMemorySize, GEMM_SMEM);
    cudaFuncSetAttribute(attn_mma_kernel,
                         cudaFuncAttributeMaxDynamicSharedMemorySize, ATTN_SMEM);

    const int convA_blocks = (MTOK * DIM / 4) / 256;   // 16384
    const int convW_blocks = (DIM * DIM / 4) / 256;    // 4096
    dim3 gemm_grid(DIM / 128, MTOK / 128);             // (16, 64)

    // Q projection
    f2h_kernel<<<convW_blocks, 256>>>(Wq, gw16);
    f2h_kernel<<<convA_blocks, 256>>>(query, ga16);
    gemm_mma_kernel<<<gemm_grid, 256, GEMM_SMEM>>>(ga16, gw16, bq, gq, DIM);
    // K projection
    f2h_kernel<<<convW_blocks, 256>>>(Wk, gw16);
    f2h_kernel<<<convA_blocks, 256>>>(key, ga16);
    gemm_mma_kernel<<<gemm_grid, 256, GEMM_SMEM>>>(ga16, gw16, bk, gk, DIM);
    // V projection
    f2h_kernel<<<convW_blocks, 256>>>(Wv, gw16);
    f2h_kernel<<<convA_blocks, 256>>>(value, ga16);
    gemm_mma_kernel<<<gemm_grid, 256, GEMM_SMEM>>>(ga16, gw16, bv, gv, DIM);

    // per-head RMSNorm on q and k
    int norm_blocks = NROWS_NORM / 8;
    rmsnorm_kernel<<<norm_blocks, 256>>>(gq, qnw, NROWS_NORM);
    rmsnorm_kernel<<<norm_blocks, 256>>>(gk, knw, NROWS_NORM);

    // attention (HMMA, split-bf16); writes fp16 activations for out-proj
    dim3 attn_grid(SEQ / QT, BATCH * HEADS);           // (16, 64)
    attn_mma_kernel<<<attn_grid, 256, ATTN_SMEM>>>(gq, gk, gv, ga16);

    // output projection (A already fp16 from attention)
    f2h_kernel<<<convW_blocks, 256>>>(Wo, gw16);
    gemm_mma_kernel<<<gemm_grid, 256, GEMM_SMEM>>>(ga16, gw16, bo, out, DIM);
}

// round 7
// speedup vs baseline: 5.0921x; 1.2753x over previous
#include <cuda_runtime.h>
#include <cuda_bf16.h>
#include <cuda_fp16.h>
#include <math.h>
#include <stdint.h>

// Problem constants
#define BATCH 4
#define SEQ   2048
#define DIM   2048
#define HEADS 16
#define HDIM  128
#define MTOK  (BATCH * SEQ)          // 8192 tokens
#define NROWS_NORM (MTOK * HEADS)    // 131072 (token,head) rows of 128

// -------------------- scratch (device globals; no cudaMalloc allowed) ------
__device__ float g_q[(size_t)MTOK * DIM];
__device__ float g_k[(size_t)MTOK * DIM];
__device__ float g_v[(size_t)MTOK * DIM];
__device__ __align__(1024) __half g_q16[(size_t)MTOK * DIM];  // rmsnormed q, fp16, pre-scaled
__device__ __align__(1024) __half g_k16[(size_t)MTOK * DIM];  // rmsnormed k, fp16
__device__ __align__(1024) __half g_a16[(size_t)MTOK * DIM];  // fp16 activations
__device__ __align__(1024) __half g_w16[(size_t)DIM * DIM];   // fp16 weights

// ===========================================================================
// helpers
// ===========================================================================
__device__ __forceinline__ uint32_t smem_u32(const void* p) {
    uint32_t a;
    asm("{ .reg .u64 t; cvta.to.shared.u64 t, %1; cvt.u32.u64 %0, t; }"
        : "=r"(a) : "l"(p));
    return a;
}

__device__ __forceinline__ void cp_async16(uint32_t saddr, const void* gptr) {
    asm volatile("cp.async.cg.shared.global [%0], [%1], 16;"
                 :: "r"(saddr), "l"(gptr) : "memory");
}

__device__ __forceinline__ void ldsm4(uint32_t& r0, uint32_t& r1,
                                      uint32_t& r2, uint32_t& r3, uint32_t addr) {
    asm volatile("ldmatrix.sync.aligned.m8n8.x4.shared.b16 {%0,%1,%2,%3}, [%4];"
                 : "=r"(r0), "=r"(r1), "=r"(r2), "=r"(r3) : "r"(addr));
}

__device__ __forceinline__ void ldsm4t(uint32_t& r0, uint32_t& r1,
                                       uint32_t& r2, uint32_t& r3, uint32_t addr) {
    asm volatile("ldmatrix.sync.aligned.m8n8.x4.trans.shared.b16 {%0,%1,%2,%3}, [%4];"
                 : "=r"(r0), "=r"(r1), "=r"(r2), "=r"(r3) : "r"(addr));
}

__device__ __forceinline__ void mma_fp16(float* c, const uint32_t* a,
                                         uint32_t b0, uint32_t b1) {
    asm volatile(
        "mma.sync.aligned.m16n8k16.row.col.f32.f16.f16.f32 "
        "{%0,%1,%2,%3}, {%4,%5,%6,%7}, {%8,%9}, {%0,%1,%2,%3};"
        : "+f"(c[0]), "+f"(c[1]), "+f"(c[2]), "+f"(c[3])
        : "r"(a[0]), "r"(a[1]), "r"(a[2]), "r"(a[3]), "r"(b0), "r"(b1));
}

// split x into fp16 hi + lo, packed pairwise
__device__ __forceinline__ void split2h(float x, float y, uint32_t& hi, uint32_t& lo) {
    __half hx = __float2half_rn(x);
    __half hy = __float2half_rn(y);
    float lx = x - __half2float(hx);
    float ly = y - __half2float(hy);
    __half2 h2 = __halves2half2(hx, hy);
    __half2 l2 = __floats2half2_rn(lx, ly);
    hi = *reinterpret_cast<uint32_t*>(&h2);
    lo = *reinterpret_cast<uint32_t*>(&l2);
}

// ===========================================================================
// fp32 -> fp16 conversion (GEMM operands)
// ===========================================================================
__global__ void __launch_bounds__(256)
f2h_kernel(const float* __restrict__ in, __half* __restrict__ out)
{
    int i = blockIdx.x * 256 + threadIdx.x;
    float4 v = ((const float4*)in)[i];
    __half2 a = __floats2half2_rn(v.x, v.y);
    __half2 b = __floats2half2_rn(v.z, v.w);
    ((__half2*)out)[2 * i]     = a;
    ((__half2*)out)[2 * i + 1] = b;
}

// ===========================================================================
// fp16 HMMA GEMM (unchanged from R6): C = A @ W^T + bias, K=2048
// ===========================================================================
#define BK       64
#define PITCHB   144
#define TILEAB   (128 * PITCHB)
#define STAGE_B  (2 * TILEAB)
#define STAGES   3
#define NCHUNK   (DIM / BK)
#define GEMM_SMEM (STAGES * STAGE_B)

__global__ void __launch_bounds__(256, 1)
gemm_mma_kernel(const __half* __restrict__ Ap, const __half* __restrict__ Bp,
                const float* __restrict__ bias, float* __restrict__ C, int N)
{
    extern __shared__ __align__(1024) char smem[];
    const uint32_t sbase = smem_u32(smem);
    const int tid  = threadIdx.x;
    const int lane = tid & 31;
    const int wid  = tid >> 5;
    const int wm   = (wid >> 2) * 64;
    const int wn   = (wid & 3) * 32;
    const int m0   = blockIdx.y * 128;
    const int n0   = blockIdx.x * 128;

    const __half* Abase = Ap + (size_t)m0 * DIM;
    const __half* Bbase = Bp + (size_t)n0 * DIM;

    const int lrow = tid >> 1;
    const int lcol = (tid & 1) * 4;
    auto load_tile = [&](int s, int c) {
        const uint32_t sa = sbase + s * STAGE_B;
        const uint32_t sb = sa + TILEAB;
        const __half* Ag = Abase + (size_t)lrow * DIM + c * BK + lcol * 8;
        const __half* Bg = Bbase + (size_t)lrow * DIM + c * BK + lcol * 8;
        const uint32_t so = lrow * PITCHB + lcol * 16;
        #pragma unroll
        for (int i = 0; i < 4; i++) {
            cp_async16(sa + so + i * 16, Ag + i * 8);
            cp_async16(sb + so + i * 16, Bg + i * 8);
        }
        asm volatile("cp.async.commit_group;" ::: "memory");
    };

    float acc[4][4][4];
    #pragma unroll
    for (int mi = 0; mi < 4; mi++)
        #pragma unroll
        for (int ni = 0; ni < 4; ni++)
            #pragma unroll
            for (int r = 0; r < 4; r++) acc[mi][ni][r] = 0.f;

    load_tile(0, 0);
    load_tile(1, 1);

    const uint32_t arow = wm + (lane & 15);
    const uint32_t brow = wn + (lane & 15);
    const uint32_t koff = (lane >> 4) * 16;

    for (int c = 0; c < NCHUNK; c++) {
        const int s = c % STAGES;
        asm volatile("cp.async.wait_group 1;" ::: "memory");
        __syncthreads();

        const uint32_t sa = sbase + s * STAGE_B + arow * PITCHB + koff;
        const uint32_t sb = sbase + s * STAGE_B + TILEAB + brow * PITCHB + koff;

        #pragma unroll
        for (int ks = 0; ks < 4; ks++) {
            uint32_t a[4][4];
            #pragma unroll
            for (int mi = 0; mi < 4; mi++)
                ldsm4(a[mi][0], a[mi][1], a[mi][2], a[mi][3],
                      sa + mi * 16 * PITCHB + ks * 32);
            uint32_t b[2][4];
            #pragma unroll
            for (int nb = 0; nb < 2; nb++)
                ldsm4(b[nb][0], b[nb][1], b[nb][2], b[nb][3],
                      sb + nb * 16 * PITCHB + ks * 32);
            #pragma unroll
            for (int mi = 0; mi < 4; mi++)
                #pragma unroll
                for (int ni = 0; ni < 4; ni++)
                    mma_fp16(acc[mi][ni], a[mi],
                             b[ni >> 1][ni & 1], b[ni >> 1][(ni & 1) + 2]);
        }

        __syncthreads();
        const int y = c + 2;
        if (y < NCHUNK) load_tile(y % STAGES, y);
        else asm volatile("cp.async.commit_group;" ::: "memory");
    }

    #pragma unroll
    for (int mi = 0; mi < 4; mi++) {
        const int r = m0 + wm + mi * 16 + (lane >> 2);
        #pragma unroll
        for (int ni = 0; ni < 4; ni++) {
            const int col = n0 + wn + ni * 8 + (lane & 3) * 2;
            float2 v0, v1;
            v0.x = acc[mi][ni][0] + bias[col];
            v0.y = acc[mi][ni][1] + bias[col + 1];
            v1.x = acc[mi][ni][2] + bias[col];
            v1.y = acc[mi][ni][3] + bias[col + 1];
            *(float2*)&C[(size_t)r * N + col]       = v0;
            *(float2*)&C[(size_t)(r + 8) * N + col] = v1;
        }
    }
}

// ---------------------------------------------------------------------------
// RMSNorm over head_dim=128 -> fp16 output (optional extra scale folded in)
// ---------------------------------------------------------------------------
__global__ void __launch_bounds__(256)
rmsnorm_h_kernel(const float* __restrict__ x, const float* __restrict__ w,
                 __half* __restrict__ out, int nrows, float outscale)
{
    int gwarp = (blockIdx.x * blockDim.x + threadIdx.x) >> 5;
    int lane  = threadIdx.x & 31;
    if (gwarp >= nrows) return;

    float4 v = *(const float4*)&x[(size_t)gwarp * 128 + lane * 4];
    float ss = v.x * v.x + v.y * v.y + v.z * v.z + v.w * v.w;
#pragma unroll
    for (int off = 16; off >= 1; off >>= 1)
        ss += __shfl_xor_sync(0xffffffffu, ss, off);
    float r = rsqrtf(ss * (1.0f / 128.0f) + 1e-6f) * outscale;
    float4 wv = *(const float4*)&w[lane * 4];
    __half2 h0 = __floats2half2_rn(v.x * r * wv.x, v.y * r * wv.y);
    __half2 h1 = __floats2half2_rn(v.z * r * wv.z, v.w * r * wv.w);
    uint2 pk;
    pk.x = *reinterpret_cast<uint32_t*>(&h0);
    pk.y = *reinterpret_cast<uint32_t*>(&h1);
    *(uint2*)&out[(size_t)gwarp * 128 + lane * 4] = pk;
}

// ===========================================================================
// fp16 flash attention. CTA = one (b,h), 128 q rows; KV in 64-row tiles.
// S = Q16.K16^T (single fp16 pass); O += P16.(Vhi + Vlo) (2-term, V exact).
// Q/K staged by cp.async (pre-converted fp16); V split during staging.
// ===========================================================================
#define QT   128
#define KT   64
#define APIT 272
#define SQ_OFF 0
#define SK_OFF (QT * APIT)                    // 34816
#define VH_OFF (SK_OFF + KT * APIT)           // 52224
#define VL_OFF (VH_OFF + KT * APIT)           // 69632
#define ATTN_SMEM (VL_OFF + KT * APIT)        // 87040

__global__ void __launch_bounds__(256, 1)
attn_mma_kernel(const __half* __restrict__ Qg, const __half* __restrict__ Kg,
                const float* __restrict__ Vg, __half* __restrict__ Og)
{
    extern __shared__ __align__(1024) char asmem[];
    char* sp = asmem;
    const uint32_t sb = smem_u32(asmem);

    const int tid  = threadIdx.x;
    const int lane = tid & 31;
    const int wid  = tid >> 5;
    const int wm   = wid * 16;
    const int sq0  = blockIdx.x * QT;
    const int b    = blockIdx.y >> 4;
    const int h    = blockIdx.y & 15;

    const __half* Qb = Qg + (size_t)(b * SEQ + sq0) * DIM + h * HDIM;
    const __half* Kb = Kg + (size_t)b * SEQ * DIM + h * HDIM;
    const float*  Vb = Vg + (size_t)b * SEQ * DIM + h * HDIM;

    // ---- stage Q via cp.async: 128 rows x 16 chunks of 16B ----
    #pragma unroll
    for (int i = 0; i < 8; i++) {
        int idx = tid + i * 256;
        int row = idx >> 4;
        int c16 = idx & 15;
        cp_async16(sb + SQ_OFF + row * APIT + c16 * 16,
                   Qb + (size_t)row * DIM + c16 * 8);
    }

    float Sf[8][4];
    float Of[16][4];
    #pragma unroll
    for (int j = 0; j < 16; j++)
        #pragma unroll
        for (int r = 0; r < 4; r++) Of[j][r] = 0.f;
    float m0 = -1e30f, m1 = -1e30f, l0 = 0.f, l1 = 0.f;

    const uint32_t qoff = (wm + (lane & 15)) * APIT + (lane >> 4) * 16;
    const uint32_t boff = ((lane & 7) + ((lane >> 4) << 3)) * APIT + ((lane >> 3) & 1) * 16;
    const uint32_t voff = ((lane & 7) + ((lane >> 3) & 1) * 8) * APIT + (lane >> 4) * 16;

    for (int kt = 0; kt < SEQ / KT; kt++) {
        __syncthreads();   // prior tile's reads of sK/sV done

        // ---- stage K via cp.async: 64 rows x 16 chunks ----
        const __half* Kt = Kb + (size_t)(kt * KT) * DIM;
        #pragma unroll
        for (int i = 0; i < 4; i++) {
            int idx = tid + i * 256;
            int row = idx >> 4;
            int c16 = idx & 15;
            cp_async16(sb + SK_OFF + row * APIT + c16 * 16,
                       Kt + (size_t)row * DIM + c16 * 8);
        }
        asm volatile("cp.async.commit_group;" ::: "memory");

        // ---- stage V (fp32 -> fp16 hi/lo split) ----
        const float* Vt = Vb + (size_t)(kt * KT) * DIM;
        #pragma unroll
        for (int i = 0; i < 8; i++) {
            int idx = tid + i * 256;
            int row = idx >> 5;
            int c4  = idx & 31;
            float4 vv = *(const float4*)&Vt[(size_t)row * DIM + c4 * 4];
            uint32_t h01, l01, h23, l23;
            split2h(vv.x, vv.y, h01, l01);
            split2h(vv.z, vv.w, h23, l23);
            uint32_t off = row * APIT + c4 * 8;
            *(uint2*)(sp + VH_OFF + off) = make_uint2(h01, h23);
            *(uint2*)(sp + VL_OFF + off) = make_uint2(l01, l23);
        }
        asm volatile("cp.async.wait_group 0;" ::: "memory");
        __syncthreads();

        // ---- S = Q.K^T single fp16 pass (k=128 over 8 steps) ----
        #pragma unroll
        for (int j = 0; j < 8; j++)
            #pragma unroll
            for (int r = 0; r < 4; r++) Sf[j][r] = 0.f;

        const uint32_t abase = sb + SQ_OFF + qoff;
        const uint32_t bbase = sb + SK_OFF + boff;
        #pragma unroll
        for (int ks = 0; ks < 8; ks++) {
            uint32_t a[4];
            ldsm4(a[0], a[1], a[2], a[3], abase + ks * 32);
            #pragma unroll
            for (int g = 0; g < 4; g++) {
                uint32_t r0, r1, r2, r3;
                ldsm4(r0, r1, r2, r3, bbase + g * 16 * APIT + ks * 32);
                mma_fp16(Sf[2 * g],     a, r0, r1);
                mma_fp16(Sf[2 * g + 1], a, r2, r3);
            }
        }

        // ---- online softmax ----
        float rmax0 = -1e30f, rmax1 = -1e30f;
        #pragma unroll
        for (int j = 0; j < 8; j++) {
            rmax0 = fmaxf(rmax0, fmaxf(Sf[j][0], Sf[j][1]));
            rmax1 = fmaxf(rmax1, fmaxf(Sf[j][2], Sf[j][3]));
        }
        rmax0 = fmaxf(rmax0, __shfl_xor_sync(0xffffffffu, rmax0, 1));
        rmax0 = fmaxf(rmax0, __shfl_xor_sync(0xffffffffu, rmax0, 2));
        rmax1 = fmaxf(rmax1, __shfl_xor_sync(0xffffffffu, rmax1, 1));
        rmax1 = fmaxf(rmax1, __shfl_xor_sync(0xffffffffu, rmax1, 2));

        float mn0 = fmaxf(m0, rmax0);
        float mn1 = fmaxf(m1, rmax1);
        float al0 = __expf(m0 - mn0);
        float al1 = __expf(m1 - mn1);
        m0 = mn0; m1 = mn1;

        float rs0 = 0.f, rs1 = 0.f;
        uint32_t ph[8][2];
        #pragma unroll
        for (int j = 0; j < 8; j++) {
            float p0 = __expf(Sf[j][0] - m0);
            float p1 = __expf(Sf[j][1] - m0);
            float p2 = __expf(Sf[j][2] - m1);
            float p3 = __expf(Sf[j][3] - m1);
            rs0 += p0 + p1;
            rs1 += p2 + p3;
            __half2 h0 = __floats2half2_rn(p0, p1);
            __half2 h1 = __floats2half2_rn(p2, p3);
            ph[j][0] = *reinterpret_cast<uint32_t*>(&h0);
            ph[j][1] = *reinterpret_cast<uint32_t*>(&h1);
        }
        rs0 += __shfl_xor_sync(0xffffffffu, rs0, 1);
        rs0 += __shfl_xor_sync(0xffffffffu, rs0, 2);
        rs1 += __shfl_xor_sync(0xffffffffu, rs1, 1);
        rs1 += __shfl_xor_sync(0xffffffffu, rs1, 2);
        l0 = l0 * al0 + rs0;
        l1 = l1 * al1 + rs1;

        #pragma unroll
        for (int j = 0; j < 16; j++) {
            Of[j][0] *= al0; Of[j][1] *= al0;
            Of[j][2] *= al1; Of[j][3] *= al1;
        }

        // ---- O += P.(Vhi + Vlo) ----
        const uint32_t vhb = sb + VH_OFF + voff;
        const uint32_t vlb = sb + VL_OFF + voff;
        #pragma unroll
        for (int ks = 0; ks < 4; ks++) {
            uint32_t pa[4] = { ph[2 * ks][0], ph[2 * ks][1],
                               ph[2 * ks + 1][0], ph[2 * ks + 1][1] };
            #pragma unroll
            for (int g = 0; g < 8; g++) {
                uint32_t vh0, vh1, vh2, vh3, vl0, vl1, vl2, vl3;
                ldsm4t(vh0, vh1, vh2, vh3, vhb + ks * 16 * APIT + g * 32);
                ldsm4t(vl0, vl1, vl2, vl3, vlb + ks * 16 * APIT + g * 32);
                mma_fp16(Of[2 * g],     pa, vh0, vh1);
                mma_fp16(Of[2 * g + 1], pa, vh2, vh3);
                mma_fp16(Of[2 * g],     pa, vl0, vl1);
                mma_fp16(Of[2 * g + 1], pa, vl2, vl3);
            }
        }
    }

    // ---- normalize and store as fp16 (out-projection activation) ----
    const float inv0 = 1.0f / l0;
    const float inv1 = 1.0f / l1;
    const int r  = lane >> 2;
    const int c2 = (lane & 3) * 2;
    __half* Ob = Og + (size_t)(b * SEQ + sq0 + wm) * DIM + h * HDIM;
    #pragma unroll
    for (int j = 0; j < 16; j++) {
        const int col = j * 8 + c2;
        __half2 v0 = __floats2half2_rn(Of[j][0] * inv0, Of[j][1] * inv0);
        __half2 v1 = __floats2half2_rn(Of[j][2] * inv1, Of[j][3] * inv1);
        *(__half2*)&Ob[(size_t)r * DIM + col]       = v0;
        *(__half2*)&Ob[(size_t)(r + 8) * DIM + col] = v1;
    }
}

// ---------------------------------------------------------------------------
extern "C" void kernel_launch(void* const* d_in, const int* in_sizes, int n_in,
                              void* d_out, int out_size)
{
    const float* query = (const float*)d_in[0];
    const float* key   = (const float*)d_in[1];
    const float* value = (const float*)d_in[2];
    const float* Wq    = (const float*)d_in[3];
    const float* bq    = (const float*)d_in[4];
    const float* Wk    = (const float*)d_in[5];
    const float* bk    = (const float*)d_in[6];
    const float* Wv    = (const float*)d_in[7];
    const float* bv    = (const float*)d_in[8];
    const float* Wo    = (const float*)d_in[9];
    const float* bo    = (const float*)d_in[10];
    const float* qnw   = (const float*)d_in[11];
    const float* knw   = (const float*)d_in[12];
    float* out = (float*)d_out;

    float *gq, *gk, *gv;
    __half *gq16, *gk16, *ga16, *gw16;
    cudaGetSymbolAddress((void**)&gq, g_q);
    cudaGetSymbolAddress((void**)&gk, g_k);
    cudaGetSymbolAddress((void**)&gv, g_v);
    cudaGetSymbolAddress((void**)&gq16, g_q16);
    cudaGetSymbolAddress((void**)&gk16, g_k16);
    cudaGetSymbolAddress((void**)&ga16, g_a16);
    cudaGetSymbolAddress((void**)&gw16, g_w16);

    cudaFuncSetAttribute(gemm_mma_kernel,
                         cudaFuncAttributeMaxDynamicSharedMemorySize, GEMM_SMEM);
    cudaFuncSetAttribute(attn_mma_kernel,
                         cudaFuncAttributeMaxDynamicSharedMemorySize, ATTN_SMEM);

    const int convA_blocks = (MTOK * DIM / 4) / 256;   // 16384
    const int convW_blocks = (DIM * DIM / 4) / 256;    // 4096
    dim3 gemm_grid(DIM / 128, MTOK / 128);             // (16, 64)

    // Q projection
    f2h_kernel<<<convW_blocks, 256>>>(Wq, gw16);
    f2h_kernel<<<convA_blocks, 256>>>(query, ga16);
    gemm_mma_kernel<<<gemm_grid, 256, GEMM_SMEM>>>(ga16, gw16, bq, gq, DIM);
    // K projection
    f2h_kernel<<<convW_blocks, 256>>>(Wk, gw16);
    f2h_kernel<<<convA_blocks, 256>>>(key, ga16);
    gemm_mma_kernel<<<gemm_grid, 256, GEMM_SMEM>>>(ga16, gw16, bk, gk, DIM);
    // V projection
    f2h_kernel<<<convW_blocks, 256>>>(Wv, gw16);
    f2h_kernel<<<convA_blocks, 256>>>(value, ga16);
    gemm_mma_kernel<<<gemm_grid, 256, GEMM_SMEM>>>(ga16, gw16, bv, gv, DIM);

    // per-head RMSNorm -> fp16 (q gets softmax scale folded in)
    int norm_blocks = NROWS_NORM / 8;
    rmsnorm_h_kernel<<<norm_blocks, 256>>>(gq, qnw, gq16, NROWS_NORM,
                                           0.08838834764831845f);
    rmsnorm_h_kernel<<<norm_blocks, 256>>>(gk, knw, gk16, NROWS_NORM, 1.0f);

    // attention (fp16 QK single pass, PV 2-term); writes fp16 activations
    dim3 attn_grid(SEQ / QT, BATCH * HEADS);           // (16, 64)
    attn_mma_kernel<<<attn_grid, 256, ATTN_SMEM>>>(gq16, gk16, gv, ga16);

    // output projection (A already fp16 from attention)
    f2h_kernel<<<convW_blocks, 256>>>(Wo, gw16);
    gemm_mma_kernel<<<gemm_grid, 256, GEMM_SMEM>>>(ga16, gw16, bo, out, DIM);
}

// round 9
// speedup vs baseline: 5.7383x; 1.1269x over previous
#include <cuda_runtime.h>
#include <cuda_bf16.h>
#include <cuda_fp16.h>
#include <math.h>
#include <stdint.h>

// Problem constants
#define BATCH 4
#define SEQ   2048
#define DIM   2048
#define HEADS 16
#define HDIM  128
#define MTOK  (BATCH * SEQ)          // 8192 tokens
#define NROWS_NORM (MTOK * HEADS)    // 131072 (token,head) rows of 128
#define WSLOT ((size_t)DIM * DIM)    // one weight slot (fp16)
#define ASLOT ((size_t)MTOK * DIM)   // one activation slot (fp16)

// -------------------- scratch (device globals; no cudaMalloc allowed) ------
__device__ float g_q[(size_t)MTOK * DIM];
__device__ float g_k[(size_t)MTOK * DIM];
__device__ float g_v[(size_t)MTOK * DIM];
__device__ __align__(1024) __half g_q16[ASLOT];       // rmsnormed q (pre-scaled)
__device__ __align__(1024) __half g_k16[ASLOT];       // rmsnormed k
__device__ __align__(1024) __half g_a16[3 * ASLOT];   // fp16 activations q/k/v
__device__ __align__(1024) __half g_w16[4 * WSLOT];   // fp16 weights q/k/v/o

// ===========================================================================
// helpers
// ===========================================================================
__device__ __forceinline__ uint32_t smem_u32(const void* p) {
    uint32_t a;
    asm("{ .reg .u64 t; cvta.to.shared.u64 t, %1; cvt.u32.u64 %0, t; }"
        : "=r"(a) : "l"(p));
    return a;
}

__device__ __forceinline__ void cp_async16(uint32_t saddr, const void* gptr) {
    asm volatile("cp.async.cg.shared.global [%0], [%1], 16;"
                 :: "r"(saddr), "l"(gptr) : "memory");
}

__device__ __forceinline__ void ldsm4(uint32_t& r0, uint32_t& r1,
                                      uint32_t& r2, uint32_t& r3, uint32_t addr) {
    asm volatile("ldmatrix.sync.aligned.m8n8.x4.shared.b16 {%0,%1,%2,%3}, [%4];"
                 : "=r"(r0), "=r"(r1), "=r"(r2), "=r"(r3) : "r"(addr));
}

__device__ __forceinline__ void ldsm4t(uint32_t& r0, uint32_t& r1,
                                       uint32_t& r2, uint32_t& r3, uint32_t addr) {
    asm volatile("ldmatrix.sync.aligned.m8n8.x4.trans.shared.b16 {%0,%1,%2,%3}, [%4];"
                 : "=r"(r0), "=r"(r1), "=r"(r2), "=r"(r3) : "r"(addr));
}

__device__ __forceinline__ void mma_fp16(float* c, const uint32_t* a,
                                         uint32_t b0, uint32_t b1) {
    asm volatile(
        "mma.sync.aligned.m16n8k16.row.col.f32.f16.f16.f32 "
        "{%0,%1,%2,%3}, {%4,%5,%6,%7}, {%8,%9}, {%0,%1,%2,%3};"
        : "+f"(c[0]), "+f"(c[1]), "+f"(c[2]), "+f"(c[3])
        : "r"(a[0]), "r"(a[1]), "r"(a[2]), "r"(a[3]), "r"(b0), "r"(b1));
}

// split x into fp16 hi + lo, packed pairwise
__device__ __forceinline__ void split2h(float x, float y, uint32_t& hi, uint32_t& lo) {
    __half hx = __float2half_rn(x);
    __half hy = __float2half_rn(y);
    float lx = x - __half2float(hx);
    float ly = y - __half2float(hy);
    __half2 h2 = __halves2half2(hx, hy);
    __half2 l2 = __floats2half2_rn(lx, ly);
    hi = *reinterpret_cast<uint32_t*>(&h2);
    lo = *reinterpret_cast<uint32_t*>(&l2);
}

// ===========================================================================
// batched fp32 -> fp16 conversions
// ===========================================================================
__global__ void __launch_bounds__(256)
f2h_w4_kernel(const float* __restrict__ w0, const float* __restrict__ w1,
              const float* __restrict__ w2, const float* __restrict__ w3,
              __half* __restrict__ out)
{
    int z = blockIdx.y;
    const float* in = (z == 0) ? w0 : (z == 1) ? w1 : (z == 2) ? w2 : w3;
    __half* o = out + (size_t)z * WSLOT;
    int i = blockIdx.x * 256 + threadIdx.x;
    float4 v = ((const float4*)in)[i];
    __half2 a = __floats2half2_rn(v.x, v.y);
    __half2 b = __floats2half2_rn(v.z, v.w);
    ((__half2*)o)[2 * i]     = a;
    ((__half2*)o)[2 * i + 1] = b;
}

__global__ void __launch_bounds__(256)
f2h_a3_kernel(const float* __restrict__ a0, const float* __restrict__ a1,
              const float* __restrict__ a2, __half* __restrict__ out)
{
    int z = blockIdx.y;
    const float* in = (z == 0) ? a0 : (z == 1) ? a1 : a2;
    __half* o = out + (size_t)z * ASLOT;
    int i = blockIdx.x * 256 + threadIdx.x;
    float4 v = ((const float4*)in)[i];
    __half2 a = __floats2half2_rn(v.x, v.y);
    __half2 b = __floats2half2_rn(v.z, v.w);
    ((__half2*)o)[2 * i]     = a;
    ((__half2*)o)[2 * i + 1] = b;
}

// ===========================================================================
// fp16 HMMA GEMM: C[M,N] = A[M,K] @ W[N,K]^T + bias   (K=2048)
// CTA 128(M) x 256(N), BK=64, 3-stage cp.async, 8 warps (2x4), warp 64x64.
// B ldsm lane mapping identical to A (rows lane&15, k-half lane>>4) so the
// fragment order matches b[g][ni&1] / b[g][(ni&1)+2] consumption.
// ===========================================================================
#define BK       64
#define PITCHB   144
#define TILE_A   (128 * PITCHB)               // 18432
#define TILE_B   (256 * PITCHB)               // 36864
#define STAGE_B  (TILE_A + TILE_B)            // 55296
#define STAGES   3
#define NCHUNK   (DIM / BK)                   // 32
#define GEMM_SMEM (STAGES * STAGE_B)          // 165888

__global__ void __launch_bounds__(256, 1)
gemm_mma_kernel(const __half* __restrict__ Ap, const __half* __restrict__ Bp,
                const float* __restrict__ bias, float* __restrict__ C, int N)
{
    extern __shared__ __align__(1024) char smem[];
    const uint32_t sbase = smem_u32(smem);
    const int tid  = threadIdx.x;
    const int lane = tid & 31;
    const int wid  = tid >> 5;
    const int wm   = (wid >> 2) * 64;          // 2 warp rows
    const int wn   = (wid & 3) * 64;           // 4 warp cols
    const int m0   = blockIdx.y * 128;
    const int n0   = blockIdx.x * 256;

    const __half* Abase = Ap + (size_t)m0 * DIM;
    const __half* Bbase = Bp + (size_t)n0 * DIM;

    auto load_tile = [&](int s, int c) {
        const uint32_t sa = sbase + s * STAGE_B;
        const uint32_t sbuf = sa + TILE_A;
        #pragma unroll
        for (int i = 0; i < 4; i++) {          // A: 1024 x 16B
            int idx = tid + i * 256;
            int row = idx >> 3, cc = idx & 7;
            cp_async16(sa + row * PITCHB + cc * 16,
                       Abase + (size_t)row * DIM + c * BK + cc * 8);
        }
        #pragma unroll
        for (int i = 0; i < 8; i++) {          // B: 2048 x 16B
            int idx = tid + i * 256;
            int row = idx >> 3, cc = idx & 7;
            cp_async16(sbuf + row * PITCHB + cc * 16,
                       Bbase + (size_t)row * DIM + c * BK + cc * 8);
        }
        asm volatile("cp.async.commit_group;" ::: "memory");
    };

    float acc[4][8][4];
    #pragma unroll
    for (int mi = 0; mi < 4; mi++)
        #pragma unroll
        for (int ni = 0; ni < 8; ni++)
            #pragma unroll
            for (int r = 0; r < 4; r++) acc[mi][ni][r] = 0.f;

    load_tile(0, 0);
    load_tile(1, 1);

    const uint32_t arow = wm + (lane & 15);
    const uint32_t brow = wn + (lane & 15);
    const uint32_t koff = (lane >> 4) * 16;

    for (int c = 0; c < NCHUNK; c++) {
        const int s = c % STAGES;
        asm volatile("cp.async.wait_group 1;" ::: "memory");
        __syncthreads();

        const uint32_t sa = sbase + s * STAGE_B + arow * PITCHB + koff;
        const uint32_t sb = sbase + s * STAGE_B + TILE_A + brow * PITCHB + koff;

        #pragma unroll
        for (int ks = 0; ks < 4; ks++) {
            uint32_t a[4][4];
            #pragma unroll
            for (int mi = 0; mi < 4; mi++)
                ldsm4(a[mi][0], a[mi][1], a[mi][2], a[mi][3],
                      sa + mi * 16 * PITCHB + ks * 32);
            uint32_t b[4][4];
            #pragma unroll
            for (int nb = 0; nb < 4; nb++)
                ldsm4(b[nb][0], b[nb][1], b[nb][2], b[nb][3],
                      sb + nb * 16 * PITCHB + ks * 32);
            #pragma unroll
            for (int mi = 0; mi < 4; mi++)
                #pragma unroll
                for (int ni = 0; ni < 8; ni++)
                    mma_fp16(acc[mi][ni], a[mi],
                             b[ni >> 1][ni & 1], b[ni >> 1][(ni & 1) + 2]);
        }

        __syncthreads();
        const int y = c + 2;
        if (y < NCHUNK) load_tile(y % STAGES, y);
        else asm volatile("cp.async.commit_group;" ::: "memory");
    }

    #pragma unroll
    for (int mi = 0; mi < 4; mi++) {
        const int r = m0 + wm + mi * 16 + (lane >> 2);
        #pragma unroll
        for (int ni = 0; ni < 8; ni++) {
            const int col = n0 + wn + ni * 8 + (lane & 3) * 2;
            float2 v0, v1;
            v0.x = acc[mi][ni][0] + bias[col];
            v0.y = acc[mi][ni][1] + bias[col + 1];
            v1.x = acc[mi][ni][2] + bias[col];
            v1.y = acc[mi][ni][3] + bias[col + 1];
            *(float2*)&C[(size_t)r * N + col]       = v0;
            *(float2*)&C[(size_t)(r + 8) * N + col] = v1;
        }
    }
}

// ---------------------------------------------------------------------------
// batched RMSNorm (q and k in one launch) -> fp16, optional scale folded in
// ---------------------------------------------------------------------------
__global__ void __launch_bounds__(256)
rmsnorm2_kernel(const float* __restrict__ qx, const float* __restrict__ kx,
                const float* __restrict__ qw, const float* __restrict__ kw,
                __half* __restrict__ qo, __half* __restrict__ ko, float qscale)
{
    const int which = blockIdx.y;
    const float* x = which ? kx : qx;
    const float* w = which ? kw : qw;
    __half* out    = which ? ko : qo;
    const float outscale = which ? 1.0f : qscale;

    int gwarp = (blockIdx.x * blockDim.x + threadIdx.x) >> 5;
    int lane  = threadIdx.x & 31;

    float4 v = *(const float4*)&x[(size_t)gwarp * 128 + lane * 4];
    float ss = v.x * v.x + v.y * v.y + v.z * v.z + v.w * v.w;
#pragma unroll
    for (int off = 16; off >= 1; off >>= 1)
        ss += __shfl_xor_sync(0xffffffffu, ss, off);
    float r = rsqrtf(ss * (1.0f / 128.0f) + 1e-6f) * outscale;
    float4 wv = *(const float4*)&w[lane * 4];
    __half2 h0 = __floats2half2_rn(v.x * r * wv.x, v.y * r * wv.y);
    __half2 h1 = __floats2half2_rn(v.z * r * wv.z, v.w * r * wv.w);
    uint2 pk;
    pk.x = *reinterpret_cast<uint32_t*>(&h0);
    pk.y = *reinterpret_cast<uint32_t*>(&h1);
    *(uint2*)&out[(size_t)gwarp * 128 + lane * 4] = pk;
}

// ===========================================================================
// fp16 flash attention (unchanged from R7).
// ===========================================================================
#define QT   128
#define KT   64
#define APIT 272
#define SQ_OFF 0
#define SK_OFF (QT * APIT)
#define VH_OFF (SK_OFF + KT * APIT)
#define VL_OFF (VH_OFF + KT * APIT)
#define ATTN_SMEM (VL_OFF + KT * APIT)        // 87040

__global__ void __launch_bounds__(256, 1)
attn_mma_kernel(const __half* __restrict__ Qg, const __half* __restrict__ Kg,
                const float* __restrict__ Vg, __half* __restrict__ Og)
{
    extern __shared__ __align__(1024) char asmem[];
    char* sp = asmem;
    const uint32_t sb = smem_u32(asmem);

    const int tid  = threadIdx.x;
    const int lane = tid & 31;
    const int wid  = tid >> 5;
    const int wm   = wid * 16;
    const int sq0  = blockIdx.x * QT;
    const int b    = blockIdx.y >> 4;
    const int h    = blockIdx.y & 15;

    const __half* Qb = Qg + (size_t)(b * SEQ + sq0) * DIM + h * HDIM;
    const __half* Kb = Kg + (size_t)b * SEQ * DIM + h * HDIM;
    const float*  Vb = Vg + (size_t)b * SEQ * DIM + h * HDIM;

    #pragma unroll
    for (int i = 0; i < 8; i++) {
        int idx = tid + i * 256;
        int row = idx >> 4;
        int c16 = idx & 15;
        cp_async16(sb + SQ_OFF + row * APIT + c16 * 16,
                   Qb + (size_t)row * DIM + c16 * 8);
    }

    float Sf[8][4];
    float Of[16][4];
    #pragma unroll
    for (int j = 0; j < 16; j++)
        #pragma unroll
        for (int r = 0; r < 4; r++) Of[j][r] = 0.f;
    float m0 = -1e30f, m1 = -1e30f, l0 = 0.f, l1 = 0.f;

    const uint32_t qoff = (wm + (lane & 15)) * APIT + (lane >> 4) * 16;
    const uint32_t boff = ((lane & 7) + ((lane >> 4) << 3)) * APIT + ((lane >> 3) & 1) * 16;
    const uint32_t voff = ((lane & 7) + ((lane >> 3) & 1) * 8) * APIT + (lane >> 4) * 16;

    for (int kt = 0; kt < SEQ / KT; kt++) {
        __syncthreads();

        const __half* Kt = Kb + (size_t)(kt * KT) * DIM;
        #pragma unroll
        for (int i = 0; i < 4; i++) {
            int idx = tid + i * 256;
            int row = idx >> 4;
            int c16 = idx & 15;
            cp_async16(sb + SK_OFF + row * APIT + c16 * 16,
                       Kt + (size_t)row * DIM + c16 * 8);
        }
        asm volatile("cp.async.commit_group;" ::: "memory");

        const float* Vt = Vb + (size_t)(kt * KT) * DIM;
        #pragma unroll
        for (int i = 0; i < 8; i++) {
            int idx = tid + i * 256;
            int row = idx >> 5;
            int c4  = idx & 31;
            float4 vv = *(const float4*)&Vt[(size_t)row * DIM + c4 * 4];
            uint32_t h01, l01, h23, l23;
            split2h(vv.x, vv.y, h01, l01);
            split2h(vv.z, vv.w, h23, l23);
            uint32_t off = row * APIT + c4 * 8;
            *(uint2*)(sp + VH_OFF + off) = make_uint2(h01, h23);
            *(uint2*)(sp + VL_OFF + off) = make_uint2(l01, l23);
        }
        asm volatile("cp.async.wait_group 0;" ::: "memory");
        __syncthreads();

        #pragma unroll
        for (int j = 0; j < 8; j++)
            #pragma unroll
            for (int r = 0; r < 4; r++) Sf[j][r] = 0.f;

        const uint32_t abase = sb + SQ_OFF + qoff;
        const uint32_t bbase = sb + SK_OFF + boff;
        #pragma unroll
        for (int ks = 0; ks < 8; ks++) {
            uint32_t a[4];
            ldsm4(a[0], a[1], a[2], a[3], abase + ks * 32);
            #pragma unroll
            for (int g = 0; g < 4; g++) {
                uint32_t r0, r1, r2, r3;
                ldsm4(r0, r1, r2, r3, bbase + g * 16 * APIT + ks * 32);
                mma_fp16(Sf[2 * g],     a, r0, r1);
                mma_fp16(Sf[2 * g + 1], a, r2, r3);
            }
        }

        float rmax0 = -1e30f, rmax1 = -1e30f;
        #pragma unroll
        for (int j = 0; j < 8; j++) {
            rmax0 = fmaxf(rmax0, fmaxf(Sf[j][0], Sf[j][1]));
            rmax1 = fmaxf(rmax1, fmaxf(Sf[j][2], Sf[j][3]));
        }
        rmax0 = fmaxf(rmax0, __shfl_xor_sync(0xffffffffu, rmax0, 1));
        rmax0 = fmaxf(rmax0, __shfl_xor_sync(0xffffffffu, rmax0, 2));
        rmax1 = fmaxf(rmax1, __shfl_xor_sync(0xffffffffu, rmax1, 1));
        rmax1 = fmaxf(rmax1, __shfl_xor_sync(0xffffffffu, rmax1, 2));

        float mn0 = fmaxf(m0, rmax0);
        float mn1 = fmaxf(m1, rmax1);
        float al0 = __expf(m0 - mn0);
        float al1 = __expf(m1 - mn1);
        m0 = mn0; m1 = mn1;

        float rs0 = 0.f, rs1 = 0.f;
        uint32_t ph[8][2];
        #pragma unroll
        for (int j = 0; j < 8; j++) {
            float p0 = __expf(Sf[j][0] - m0);
            float p1 = __expf(Sf[j][1] - m0);
            float p2 = __expf(Sf[j][2] - m1);
            float p3 = __expf(Sf[j][3] - m1);
            rs0 += p0 + p1;
            rs1 += p2 + p3;
            __half2 h0 = __floats2half2_rn(p0, p1);
            __half2 h1 = __floats2half2_rn(p2, p3);
            ph[j][0] = *reinterpret_cast<uint32_t*>(&h0);
            ph[j][1] = *reinterpret_cast<uint32_t*>(&h1);
        }
        rs0 += __shfl_xor_sync(0xffffffffu, rs0, 1);
        rs0 += __shfl_xor_sync(0xffffffffu, rs0, 2);
        rs1 += __shfl_xor_sync(0xffffffffu, rs1, 1);
        rs1 += __shfl_xor_sync(0xffffffffu, rs1, 2);
        l0 = l0 * al0 + rs0;
        l1 = l1 * al1 + rs1;

        #pragma unroll
        for (int j = 0; j < 16; j++) {
            Of[j][0] *= al0; Of[j][1] *= al0;
            Of[j][2] *= al1; Of[j][3] *= al1;
        }

        const uint32_t vhb = sb + VH_OFF + voff;
        const uint32_t vlb = sb + VL_OFF + voff;
        #pragma unroll
        for (int ks = 0; ks < 4; ks++) {
            uint32_t pa[4] = { ph[2 * ks][0], ph[2 * ks][1],
                               ph[2 * ks + 1][0], ph[2 * ks + 1][1] };
            #pragma unroll
            for (int g = 0; g < 8; g++) {
                uint32_t vh0, vh1, vh2, vh3, vl0, vl1, vl2, vl3;
                ldsm4t(vh0, vh1, vh2, vh3, vhb + ks * 16 * APIT + g * 32);
                ldsm4t(vl0, vl1, vl2, vl3, vlb + ks * 16 * APIT + g * 32);
                mma_fp16(Of[2 * g],     pa, vh0, vh1);
                mma_fp16(Of[2 * g + 1], pa, vh2, vh3);
                mma_fp16(Of[2 * g],     pa, vl0, vl1);
                mma_fp16(Of[2 * g + 1], pa, vl2, vl3);
            }
        }
    }

    const float inv0 = 1.0f / l0;
    const float inv1 = 1.0f / l1;
    const int r  = lane >> 2;
    const int c2 = (lane & 3) * 2;
    __half* Ob = Og + (size_t)(b * SEQ + sq0 + wm) * DIM + h * HDIM;
    #pragma unroll
    for (int j = 0; j < 16; j++) {
        const int col = j * 8 + c2;
        __half2 v0 = __floats2half2_rn(Of[j][0] * inv0, Of[j][1] * inv0);
        __half2 v1 = __floats2half2_rn(Of[j][2] * inv1, Of[j][3] * inv1);
        *(__half2*)&Ob[(size_t)r * DIM + col]       = v0;
        *(__half2*)&Ob[(size_t)(r + 8) * DIM + col] = v1;
    }
}

// ---------------------------------------------------------------------------
extern "C" void kernel_launch(void* const* d_in, const int* in_sizes, int n_in,
                              void* d_out, int out_size)
{
    const float* query = (const float*)d_in[0];
    const float* key   = (const float*)d_in[1];
    const float* value = (const float*)d_in[2];
    const float* Wq    = (const float*)d_in[3];
    const float* bq    = (const float*)d_in[4];
    const float* Wk    = (const float*)d_in[5];
    const float* bk    = (const float*)d_in[6];
    const float* Wv    = (const float*)d_in[7];
    const float* bv    = (const float*)d_in[8];
    const float* Wo    = (const float*)d_in[9];
    const float* bo    = (const float*)d_in[10];
    const float* qnw   = (const float*)d_in[11];
    const float* knw   = (const float*)d_in[12];
    float* out = (float*)d_out;

    float *gq, *gk, *gv;
    __half *gq16, *gk16, *ga16, *gw16;
    cudaGetSymbolAddress((void**)&gq, g_q);
    cudaGetSymbolAddress((void**)&gk, g_k);
    cudaGetSymbolAddress((void**)&gv, g_v);
    cudaGetSymbolAddress((void**)&gq16, g_q16);
    cudaGetSymbolAddress((void**)&gk16, g_k16);
    cudaGetSymbolAddress((void**)&ga16, g_a16);
    cudaGetSymbolAddress((void**)&gw16, g_w16);

    cudaFuncSetAttribute(gemm_mma_kernel,
                         cudaFuncAttributeMaxDynamicSharedMemorySize, GEMM_SMEM);
    cudaFuncSetAttribute(attn_mma_kernel,
                         cudaFuncAttributeMaxDynamicSharedMemorySize, ATTN_SMEM);

    // 1) convert all weights + all activations (2 launches)
    dim3 wgrid((DIM * DIM / 4) / 256, 4);              // (4096, 4)
    f2h_w4_kernel<<<wgrid, 256>>>(Wq, Wk, Wv, Wo, gw16);
    dim3 agrid((MTOK * DIM / 4) / 256, 3);             // (16384, 3)
    f2h_a3_kernel<<<agrid, 256>>>(query, key, value, ga16);

    // 2) QKV projections (back-to-back)
    dim3 gemm_grid(DIM / 256, MTOK / 128);             // (8, 64)
    gemm_mma_kernel<<<gemm_grid, 256, GEMM_SMEM>>>(ga16,             gw16,             bq, gq, DIM);
    gemm_mma_kernel<<<gemm_grid, 256, GEMM_SMEM>>>(ga16 + ASLOT,     gw16 + WSLOT,     bk, gk, DIM);
    gemm_mma_kernel<<<gemm_grid, 256, GEMM_SMEM>>>(ga16 + 2 * ASLOT, gw16 + 2 * WSLOT, bv, gv, DIM);

    // 3) both RMSNorms in one launch (q gets softmax scale folded in)
    dim3 ngrid(NROWS_NORM / 8, 2);
    rmsnorm2_kernel<<<ngrid, 256>>>(gq, gk, qnw, knw, gq16, gk16,
                                    0.08838834764831845f);

    // 4) attention; writes fp16 activations into slot 0
    dim3 attn_grid(SEQ / QT, BATCH * HEADS);           // (16, 64)
    attn_mma_kernel<<<attn_grid, 256, ATTN_SMEM>>>(gq16, gk16, gv, ga16);

    // 5) output projection
    gemm_mma_kernel<<<gemm_grid, 256, GEMM_SMEM>>>(ga16, gw16 + 3 * WSLOT, bo, out, DIM);
}